// round 3
// baseline (speedup 1.0000x reference)
#include <cuda_runtime.h>

// ---------------------------------------------------------------------------
// GCN5: 5-layer GCN, N=100000 nodes, E=3.2M edges, dims 32->256->1024->1024->256->6
// Aggregate in the smaller of (in,out) dim per layer using A(hW) == (A h) W.
// Self-loop term + bias folded into buffer init. Scatter-add via 128-bit
// vector atomics. edge_index dtype (int32 vs int64) detected at runtime.
// ---------------------------------------------------------------------------

__device__ float g_bufA[102400000];   // 100000 * 1024
__device__ float g_bufB[102400000];   // 100000 * 1024
__device__ float g_z6[600064];        // 100000 * 6 (+pad)
__device__ float g_deg[100000];
__device__ float g_dinv[100000];
__device__ int   g_is64;              // 1 if edge_index is int64, 0 if int32

// ---------------------------------------------------------------------------
// Detect edge_index dtype: int64 little-endian with ids < 2^31 has the high
// 32-bit word of every element == 0. int32 data has node ids there (~never
// all zero over 4096 samples).
__global__ void k_detect(const unsigned* __restrict__ w, int npairs) {
    __shared__ int any;
    if (threadIdx.x == 0) any = 0;
    __syncthreads();
    for (int i = threadIdx.x; i < npairs; i += blockDim.x)
        if (w[2 * i + 1] != 0u) any = 1;   // benign race
    __syncthreads();
    if (threadIdx.x == 0) g_is64 = (any == 0) ? 1 : 0;
}

__device__ __forceinline__ void edge_get(const void* ei, int E, int e, int& s, int& d) {
    if (g_is64) {
        const long long* p = (const long long*)ei;
        s = (int)p[e];
        d = (int)p[E + e];
    } else {
        const int* p = (const int*)ei;
        s = p[e];
        d = p[E + e];
    }
}

// ---------------------------------------------------------------------------

__global__ void k_zero(float* __restrict__ p, int n) {
    int i = blockIdx.x * blockDim.x + threadIdx.x;
    if (i < n) p[i] = 0.f;
}

__global__ void k_deg(const void* __restrict__ ei, float* __restrict__ deg, int E) {
    int e = blockIdx.x * blockDim.x + threadIdx.x;
    if (e >= E) return;
    int s, d;
    edge_get(ei, E, e, s, d);
    atomicAdd(&deg[d], 1.0f);
}

__global__ void k_dinv(const float* __restrict__ deg, float* __restrict__ dinv, int n) {
    int i = blockIdx.x * blockDim.x + threadIdx.x;
    if (i < n) dinv[i] = rsqrtf(deg[i] + 1.0f);   // +1 = self loop
}

// out[node] = h[node] * dinv[node]^2 (+ bias)  — self-loop term, inits buffer
template<int F>
__global__ void k_selfinit(const float* __restrict__ h, float* __restrict__ out,
                           const float* __restrict__ dinv, const float* __restrict__ bias,
                           int n) {
    constexpr int F4 = F / 4;
    int i = blockIdx.x * blockDim.x + threadIdx.x;
    if (i >= n * F4) return;
    int node = i / F4;
    int c = i - node * F4;
    float dv = dinv[node];
    float s = dv * dv;
    float4 v = reinterpret_cast<const float4*>(h)[i];
    v.x *= s; v.y *= s; v.z *= s; v.w *= s;
    if (bias) {
        float4 b = reinterpret_cast<const float4*>(bias)[c];
        v.x += b.x; v.y += b.y; v.z += b.z; v.w += b.w;
    }
    reinterpret_cast<float4*>(out)[i] = v;
}

// out[dst] += h[src] * dinv[src]*dinv[dst], float4 lanes, 128-bit atomics
template<int F4>   // float4s per feature row; F4 in {8, 64, 256}
__global__ void k_agg(const float* __restrict__ h, float* __restrict__ out,
                      const void* __restrict__ ei,
                      const float* __restrict__ dinv, int E) {
    constexpr int EPB = 256 / F4;   // edges per block
    int e = blockIdx.x * EPB + threadIdx.x / F4;
    int lane = threadIdx.x % F4;
    if (e >= E) return;
    int s, d;
    edge_get(ei, E, e, s, d);
    float nrm = dinv[s] * dinv[d];
    float4 v = reinterpret_cast<const float4*>(h)[(long long)s * F4 + lane];
    v.x *= nrm; v.y *= nrm; v.z *= nrm; v.w *= nrm;
    float4* p = reinterpret_cast<float4*>(out) + ((long long)d * F4 + lane);
    atomicAdd(p, v);   // sm_90+ 128-bit reduction
}

// ---------------------------------------------------------------------------
// Tiled SGEMM: C[M,N] = A[M,K] @ B[K,N] (+bias) (+relu).  BM=BN=128, BK=8, 8x8/thread
// ---------------------------------------------------------------------------
template<bool RELU_OUT, bool HAS_BIAS>
__global__ __launch_bounds__(256)
void k_sgemm(const float* __restrict__ A, const float* __restrict__ B,
             const float* __restrict__ bias, float* __restrict__ C,
             int M, int K, int N) {
    constexpr int BM = 128, BN = 128, BK = 8, TM = 8, TN = 8;
    __shared__ float As[BK][BM];
    __shared__ float Bs[BK][BN];
    int tid = threadIdx.x;
    int tr = tid / 16;          // 0..15
    int tc = tid % 16;          // 0..15

    float acc[TM][TN];
#pragma unroll
    for (int i = 0; i < TM; i++)
#pragma unroll
        for (int j = 0; j < TN; j++) acc[i][j] = 0.f;

    int aRow = tid >> 1;              // 0..127
    int aCol = (tid & 1) << 2;        // 0 or 4
    int bRow = tid >> 5;              // 0..7
    int bCol = (tid & 31) << 2;       // 0..124

    long long aGRow = (long long)blockIdx.y * BM + aRow;
    const bool aValid = aGRow < M;
    const float* Aptr = A + aGRow * (long long)K + aCol;
    const float* Bptr = B + (long long)bRow * N + (long long)blockIdx.x * BN + bCol;

    for (int k0 = 0; k0 < K; k0 += BK) {
        float4 av = make_float4(0.f, 0.f, 0.f, 0.f);
        if (aValid) av = *reinterpret_cast<const float4*>(Aptr + k0);
        As[aCol + 0][aRow] = av.x;
        As[aCol + 1][aRow] = av.y;
        As[aCol + 2][aRow] = av.z;
        As[aCol + 3][aRow] = av.w;
        float4 bv = *reinterpret_cast<const float4*>(Bptr + (long long)k0 * N);
        *reinterpret_cast<float4*>(&Bs[bRow][bCol]) = bv;
        __syncthreads();
#pragma unroll
        for (int k = 0; k < BK; k++) {
            float rm[TM], rn[TN];
#pragma unroll
            for (int i = 0; i < TM; i++) rm[i] = As[k][tr * TM + i];
#pragma unroll
            for (int j = 0; j < TN; j++) rn[j] = Bs[k][tc * TN + j];
#pragma unroll
            for (int i = 0; i < TM; i++)
#pragma unroll
                for (int j = 0; j < TN; j++)
                    acc[i][j] += rm[i] * rn[j];
        }
        __syncthreads();
    }

#pragma unroll
    for (int i = 0; i < TM; i++) {
        long long row = (long long)blockIdx.y * BM + tr * TM + i;
        if (row >= M) continue;
#pragma unroll
        for (int j = 0; j < TN; j += 4) {
            int col = blockIdx.x * BN + tc * TN + j;
            float4 v = make_float4(acc[i][j], acc[i][j + 1], acc[i][j + 2], acc[i][j + 3]);
            if (HAS_BIAS) {
                float4 bb = *reinterpret_cast<const float4*>(bias + col);
                v.x += bb.x; v.y += bb.y; v.z += bb.z; v.w += bb.w;
            }
            if (RELU_OUT) {
                v.x = fmaxf(v.x, 0.f); v.y = fmaxf(v.y, 0.f);
                v.z = fmaxf(v.z, 0.f); v.w = fmaxf(v.w, 0.f);
            }
            *reinterpret_cast<float4*>(C + row * (long long)N + col) = v;
        }
    }
}

// ---------------------------------------------------------------------------
// Layer-5 GEMM: z = relu(A[M,256]) @ W[256,6]. One warp per row.
// ---------------------------------------------------------------------------
__global__ void k_gemm_relu_256x6(const float* __restrict__ A, const float* __restrict__ W,
                                  float* __restrict__ C, int M) {
    __shared__ float Ws[256 * 6];
    for (int i = threadIdx.x; i < 256 * 6; i += blockDim.x) Ws[i] = W[i];
    __syncthreads();
    int warp = threadIdx.x >> 5;
    int lane = threadIdx.x & 31;
    long long row = (long long)blockIdx.x * 8 + warp;
    if (row >= M) return;
    float a0 = 0.f, a1 = 0.f, a2 = 0.f, a3 = 0.f, a4 = 0.f, a5 = 0.f;
    const float* a = A + row * 256;
#pragma unroll
    for (int k0 = 0; k0 < 256; k0 += 32) {
        float av = fmaxf(a[k0 + lane], 0.f);
        const float* w = &Ws[(k0 + lane) * 6];
        a0 += av * w[0]; a1 += av * w[1]; a2 += av * w[2];
        a3 += av * w[3]; a4 += av * w[4]; a5 += av * w[5];
    }
#pragma unroll
    for (int off = 16; off > 0; off >>= 1) {
        a0 += __shfl_down_sync(0xffffffffu, a0, off);
        a1 += __shfl_down_sync(0xffffffffu, a1, off);
        a2 += __shfl_down_sync(0xffffffffu, a2, off);
        a3 += __shfl_down_sync(0xffffffffu, a3, off);
        a4 += __shfl_down_sync(0xffffffffu, a4, off);
        a5 += __shfl_down_sync(0xffffffffu, a5, off);
    }
    if (lane == 0) {
        float* c = C + row * 6;
        c[0] = a0; c[1] = a1; c[2] = a2; c[3] = a3; c[4] = a4; c[5] = a5;
    }
}

__global__ void k_selfinit6(const float* __restrict__ z, float* __restrict__ out,
                            const float* __restrict__ dinv, const float* __restrict__ b, int n) {
    int i = blockIdx.x * blockDim.x + threadIdx.x;
    if (i >= n * 6) return;
    int node = i / 6;
    int c = i - node * 6;
    float dv = dinv[node];
    out[i] = z[i] * dv * dv + b[c];
}

__global__ void k_agg6(const float* __restrict__ z, float* __restrict__ out,
                       const void* __restrict__ ei,
                       const float* __restrict__ dinv, int E) {
    int e = blockIdx.x * blockDim.x + threadIdx.x;
    if (e >= E) return;
    int s, d;
    edge_get(ei, E, e, s, d);
    float nrm = dinv[s] * dinv[d];
    const float* zp = z + (long long)s * 6;
    float* op = out + (long long)d * 6;
#pragma unroll
    for (int j = 0; j < 6; j++) atomicAdd(&op[j], zp[j] * nrm);
}

// ---------------------------------------------------------------------------

static inline unsigned cdiv(long long a, long long b) { return (unsigned)((a + b - 1) / b); }

extern "C" void kernel_launch(void* const* d_in, const int* in_sizes, int n_in,
                              void* d_out, int out_size) {
    const float* x      = (const float*)d_in[0];
    const void*  ei     = d_in[1];
    const float* W1 = (const float*)d_in[2];  const float* b1 = (const float*)d_in[3];
    const float* W2 = (const float*)d_in[4];  const float* b2 = (const float*)d_in[5];
    const float* W3 = (const float*)d_in[6];  const float* b3 = (const float*)d_in[7];
    const float* W4 = (const float*)d_in[8];  const float* b4 = (const float*)d_in[9];
    const float* W5 = (const float*)d_in[10]; const float* b5 = (const float*)d_in[11];

    int N = in_sizes[0] / 32;
    int E = in_sizes[1] / 2;
    float* out = (float*)d_out;

    float *bufA, *bufB, *z6, *deg, *dinv;
    cudaGetSymbolAddress((void**)&bufA, g_bufA);
    cudaGetSymbolAddress((void**)&bufB, g_bufB);
    cudaGetSymbolAddress((void**)&z6,   g_z6);
    cudaGetSymbolAddress((void**)&deg,  g_deg);
    cudaGetSymbolAddress((void**)&dinv, g_dinv);

    // --- edge dtype detection + degree / normalization ---
    int npairs = (2 * E < 8192) ? E : 4096;
    k_detect<<<1, 256>>>((const unsigned*)ei, npairs);
    k_zero<<<cdiv(N, 256), 256>>>(deg, N);
    k_deg<<<cdiv(E, 256), 256>>>(ei, deg, E);
    k_dinv<<<cdiv(N, 256), 256>>>(deg, dinv, N);

    // --- L1: t = A*x (F=32) -> bufA ; h1 = relu(t@W1 + b1) -> bufB [N,256] ---
    k_selfinit<32><<<cdiv((long long)N * 8, 256), 256>>>(x, bufA, dinv, nullptr, N);
    k_agg<8><<<cdiv(E, 32), 256>>>(x, bufA, ei, dinv, E);
    k_sgemm<true, true><<<dim3(2, cdiv(N, 128)), 256>>>(bufA, W1, b1, bufB, N, 32, 256);

    // --- L2: t = A*h1 (F=256) -> bufA ; h2 = relu(t@W2 + b2) -> bufB [N,1024] ---
    k_selfinit<256><<<cdiv((long long)N * 64, 256), 256>>>(bufB, bufA, dinv, nullptr, N);
    k_agg<64><<<cdiv(E, 4), 256>>>(bufB, bufA, ei, dinv, E);
    k_sgemm<true, true><<<dim3(8, cdiv(N, 128)), 256>>>(bufA, W2, b2, bufB, N, 256, 1024);

    // --- L3: t = A*h2 (F=1024) -> bufA ; h3 = relu(t@W3 + b3) -> bufB [N,1024] ---
    k_selfinit<1024><<<cdiv((long long)N * 256, 256), 256>>>(bufB, bufA, dinv, nullptr, N);
    k_agg<256><<<cdiv(E, 1), 256>>>(bufB, bufA, ei, dinv, E);
    k_sgemm<true, true><<<dim3(8, cdiv(N, 128)), 256>>>(bufA, W3, b3, bufB, N, 1024, 1024);

    // --- L4 (transform-first): z = h3@W4 -> bufA [N,256];
    //     t = A*z + b4 -> bufB (relu folded into L5 GEMM read) ---
    k_sgemm<false, false><<<dim3(2, cdiv(N, 128)), 256>>>(bufB, W4, nullptr, bufA, N, 1024, 256);
    k_selfinit<256><<<cdiv((long long)N * 64, 256), 256>>>(bufA, bufB, dinv, b4, N);
    k_agg<64><<<cdiv(E, 4), 256>>>(bufA, bufB, ei, dinv, E);

    // --- L5 (transform-first): z6 = relu(bufB)@W5 ; out = A*z6 + b5 ---
    k_gemm_relu_256x6<<<cdiv(N, 8), 256>>>(bufB, W5, z6, N);
    k_selfinit6<<<cdiv((long long)N * 6, 256), 256>>>(z6, out, dinv, b5, N);
    k_agg6<<<cdiv(E, 256), 256>>>(z6, out, ei, dinv, E);
}

// round 6
// speedup vs baseline: 1.3374x; 1.3374x over previous
#include <cuda_runtime.h>
#include <cuda_bf16.h>
#include <cstdint>

// ---------------------------------------------------------------------------
// GCN5: 5-layer GCN, N=100000, E=3.2M, dims 32->256->1024->1024->256->6
// R5: big GEMMs on tensor cores via portable mma.sync bf16 (3-term fp32 split).
// (tcgen05 unavailable: harness PTX targets compute_103, not 103a.)
// ---------------------------------------------------------------------------

__device__ float g_bufA[102400000];   // 100000 * 1024
__device__ float g_bufB[102400000];   // 100000 * 1024
__device__ float g_z6[600064];
__device__ float g_deg[100000];
__device__ float g_dinv[100000];
__device__ int   g_is64;

__device__ __align__(128) __nv_bfloat16 g_Ahi[102400000];
__device__ __align__(128) __nv_bfloat16 g_Alo[102400000];
__device__ __align__(128) __nv_bfloat16 g_W2h[262144], g_W2l[262144];
__device__ __align__(128) __nv_bfloat16 g_W3h[1048576], g_W3l[1048576];
__device__ __align__(128) __nv_bfloat16 g_W4h[262144], g_W4l[262144];

// ---------------------------------------------------------------------------
// edge dtype detection + graph prep
// ---------------------------------------------------------------------------
__global__ void k_detect(const unsigned* __restrict__ w, int npairs) {
    __shared__ int any;
    if (threadIdx.x == 0) any = 0;
    __syncthreads();
    for (int i = threadIdx.x; i < npairs; i += blockDim.x)
        if (w[2 * i + 1] != 0u) any = 1;
    __syncthreads();
    if (threadIdx.x == 0) g_is64 = (any == 0) ? 1 : 0;
}

__device__ __forceinline__ void edge_get(const void* ei, int E, int e, int& s, int& d) {
    if (g_is64) {
        const long long* p = (const long long*)ei;
        s = (int)p[e]; d = (int)p[E + e];
    } else {
        const int* p = (const int*)ei;
        s = p[e]; d = p[E + e];
    }
}

__global__ void k_zero(float* __restrict__ p, int n) {
    int i = blockIdx.x * blockDim.x + threadIdx.x;
    if (i < n) p[i] = 0.f;
}
__global__ void k_deg(const void* __restrict__ ei, float* __restrict__ deg, int E) {
    int e = blockIdx.x * blockDim.x + threadIdx.x;
    if (e >= E) return;
    int s, d; edge_get(ei, E, e, s, d);
    atomicAdd(&deg[d], 1.0f);
}
__global__ void k_dinv(const float* __restrict__ deg, float* __restrict__ dinv, int n) {
    int i = blockIdx.x * blockDim.x + threadIdx.x;
    if (i < n) dinv[i] = rsqrtf(deg[i] + 1.0f);
}

template<int F>
__global__ void k_selfinit(const float* __restrict__ h, float* __restrict__ out,
                           const float* __restrict__ dinv, const float* __restrict__ bias, int n) {
    constexpr int F4 = F / 4;
    int i = blockIdx.x * blockDim.x + threadIdx.x;
    if (i >= n * F4) return;
    int node = i / F4;
    int c = i - node * F4;
    float dv = dinv[node];
    float s = dv * dv;
    float4 v = reinterpret_cast<const float4*>(h)[i];
    v.x *= s; v.y *= s; v.z *= s; v.w *= s;
    if (bias) {
        float4 b = reinterpret_cast<const float4*>(bias)[c];
        v.x += b.x; v.y += b.y; v.z += b.z; v.w += b.w;
    }
    reinterpret_cast<float4*>(out)[i] = v;
}

template<int F4>
__global__ void k_agg(const float* __restrict__ h, float* __restrict__ out,
                      const void* __restrict__ ei, const float* __restrict__ dinv, int E) {
    constexpr int EPB = 256 / F4;
    int e = blockIdx.x * EPB + threadIdx.x / F4;
    int lane = threadIdx.x % F4;
    if (e >= E) return;
    int s, d; edge_get(ei, E, e, s, d);
    float nrm = dinv[s] * dinv[d];
    float4 v = reinterpret_cast<const float4*>(h)[(long long)s * F4 + lane];
    v.x *= nrm; v.y *= nrm; v.z *= nrm; v.w *= nrm;
    atomicAdd(reinterpret_cast<float4*>(out) + ((long long)d * F4 + lane), v);
}

// ---------------------------------------------------------------------------
// fp32 -> bf16 hi/lo splits
// ---------------------------------------------------------------------------
__global__ void k_asplit(const float* __restrict__ x, __nv_bfloat16* __restrict__ hi,
                         __nv_bfloat16* __restrict__ lo, long long n4) {
    long long i = blockIdx.x * (long long)blockDim.x + threadIdx.x;
    if (i >= n4) return;
    float4 v = reinterpret_cast<const float4*>(x)[i];
    __nv_bfloat16 h0 = __float2bfloat16_rn(v.x), h1 = __float2bfloat16_rn(v.y);
    __nv_bfloat16 h2 = __float2bfloat16_rn(v.z), h3 = __float2bfloat16_rn(v.w);
    __nv_bfloat16 l0 = __float2bfloat16_rn(v.x - __bfloat162float(h0));
    __nv_bfloat16 l1 = __float2bfloat16_rn(v.y - __bfloat162float(h1));
    __nv_bfloat16 l2 = __float2bfloat16_rn(v.z - __bfloat162float(h2));
    __nv_bfloat16 l3 = __float2bfloat16_rn(v.w - __bfloat162float(h3));
    reinterpret_cast<__nv_bfloat162*>(hi)[2 * i]     = __nv_bfloat162(h0, h1);
    reinterpret_cast<__nv_bfloat162*>(hi)[2 * i + 1] = __nv_bfloat162(h2, h3);
    reinterpret_cast<__nv_bfloat162*>(lo)[2 * i]     = __nv_bfloat162(l0, l1);
    reinterpret_cast<__nv_bfloat162*>(lo)[2 * i + 1] = __nv_bfloat162(l2, l3);
}

// W[K,N] -> Wt_hi/lo[N,K] (K-major rows of the transpose)
__global__ void k_wsplit(const float* __restrict__ W, __nv_bfloat16* __restrict__ th,
                         __nv_bfloat16* __restrict__ tl, int K, int N) {
    int i = blockIdx.x * blockDim.x + threadIdx.x;
    if (i >= K * N) return;
    int k = i / N, n = i - k * N;
    float w = W[i];
    __nv_bfloat16 h = __float2bfloat16_rn(w);
    __nv_bfloat16 l = __float2bfloat16_rn(w - __bfloat162float(h));
    th[(long long)n * K + k] = h;
    tl[(long long)n * K + k] = l;
}

// ---------------------------------------------------------------------------
// mma.sync bf16 GEMM: C[M,N] = (Ah+Al)@(Bh+Bl)^T, 3-term fp32-accurate.
// A [M,K] row-major, B [N,K] K-major. Tile 128x128x32, 8 warps (4Mx2N),
// warp tile 32x64 (2x8 m16n8k16). cp.async 2-stage double buffer.
// ---------------------------------------------------------------------------
__device__ __forceinline__ uint32_t smem_u32(const void* p) {
    uint32_t a;
    asm("{ .reg .u64 t; cvta.to.shared.u64 t, %1; cvt.u32.u64 %0, t; }" : "=r"(a) : "l"(p));
    return a;
}
__device__ __forceinline__ void cp16(uint32_t dst, const void* src, bool v) {
    asm volatile("cp.async.cg.shared.global [%0], [%1], 16, %2;"
                 :: "r"(dst), "l"(src), "r"(v ? 16 : 0) : "memory");
}
__device__ __forceinline__ uint32_t lds32(const __nv_bfloat16* p) {
    return *reinterpret_cast<const uint32_t*>(p);
}
__device__ __forceinline__ void mma16816(float* c, const uint32_t* a, const uint32_t* b) {
    asm volatile("mma.sync.aligned.m16n8k16.row.col.f32.bf16.bf16.f32 "
                 "{%0,%1,%2,%3}, {%4,%5,%6,%7}, {%8,%9}, {%0,%1,%2,%3};"
                 : "+f"(c[0]), "+f"(c[1]), "+f"(c[2]), "+f"(c[3])
                 : "r"(a[0]), "r"(a[1]), "r"(a[2]), "r"(a[3]), "r"(b[0]), "r"(b[1]));
}

// smem layout (bf16 units): stage s at s*20480; tiles Ah:+0 Al:+5120 Bh:+10240 Bl:+15360
// each tile 128 rows x 32 cols, row stride 40 (80B, 16B-aligned, conflict-free)
#define STG_STRIDE 20480
#define ROW_ST 40

template<bool RELU, bool HAS_BIAS>
__global__ __launch_bounds__(256)
void k_mma(const __nv_bfloat16* __restrict__ Ah, const __nv_bfloat16* __restrict__ Al,
           const __nv_bfloat16* __restrict__ Bh, const __nv_bfloat16* __restrict__ Bl,
           const float* __restrict__ bias, float* __restrict__ C,
           int M, int K, int N) {
    extern __shared__ __align__(16) __nv_bfloat16 sm[];
    const int tid = threadIdx.x;
    const int wid = tid >> 5, lane = tid & 31;
    const int wm = wid & 3, wn = wid >> 2;
    const int gid = lane >> 2, tq = lane & 3;
    const int m0 = blockIdx.y * 128, n0 = blockIdx.x * 128;

    float acc[2][8][4];
#pragma unroll
    for (int a = 0; a < 2; a++)
#pragma unroll
        for (int b = 0; b < 8; b++)
#pragma unroll
            for (int c = 0; c < 4; c++) acc[a][b][c] = 0.f;

    const int nK = K >> 5;

    // ---- async load of one 32-wide K slab into stage s ----
    auto issue = [&](int it, int s) {
        int k0 = it << 5;
#pragma unroll
        for (int i = 0; i < 2; i++) {
            int idx = tid + i * 256;          // 0..511
            int row = idx >> 2, g = idx & 3;  // row 0..127, 16B group 0..3
            uint32_t so = (uint32_t)s * STG_STRIDE + row * ROW_ST + g * 8;
            bool av = (m0 + row) < M;
            size_t gA = (size_t)(m0 + row) * K + k0 + g * 8;
            cp16(smem_u32(sm + so),          Ah + (av ? gA : 0), av);
            cp16(smem_u32(sm + so + 5120),   Al + (av ? gA : 0), av);
            size_t gB = (size_t)(n0 + row) * K + k0 + g * 8;
            cp16(smem_u32(sm + so + 10240),  Bh + gB, true);
            cp16(smem_u32(sm + so + 15360),  Bl + gB, true);
        }
        asm volatile("cp.async.commit_group;" ::: "memory");
    };

    issue(0, 0);
    for (int it = 0; it < nK; ++it) {
        if (it + 1 < nK) {
            issue(it + 1, (it + 1) & 1);
            asm volatile("cp.async.wait_group 1;" ::: "memory");
        } else {
            asm volatile("cp.async.wait_group 0;" ::: "memory");
        }
        __syncthreads();

        const __nv_bfloat16* sbase = sm + (uint32_t)(it & 1) * STG_STRIDE;
#pragma unroll
        for (int kk = 0; kk < 32; kk += 16) {
            uint32_t ah[2][4], al[2][4];
#pragma unroll
            for (int mt = 0; mt < 2; mt++) {
                const __nv_bfloat16* p = sbase + (wm * 32 + mt * 16 + gid) * ROW_ST + kk + tq * 2;
                ah[mt][0] = lds32(p);
                ah[mt][1] = lds32(p + 8 * ROW_ST);
                ah[mt][2] = lds32(p + 8);
                ah[mt][3] = lds32(p + 8 * ROW_ST + 8);
                al[mt][0] = lds32(p + 5120);
                al[mt][1] = lds32(p + 5120 + 8 * ROW_ST);
                al[mt][2] = lds32(p + 5120 + 8);
                al[mt][3] = lds32(p + 5120 + 8 * ROW_ST + 8);
            }
#pragma unroll
            for (int nt = 0; nt < 8; nt++) {
                const __nv_bfloat16* q = sbase + 10240 + (wn * 64 + nt * 8 + gid) * ROW_ST + kk + tq * 2;
                uint32_t bh[2] = { lds32(q), lds32(q + 8) };
                uint32_t bl[2] = { lds32(q + 5120), lds32(q + 5120 + 8) };
#pragma unroll
                for (int mt = 0; mt < 2; mt++) {
                    mma16816(acc[mt][nt], ah[mt], bh);
                    mma16816(acc[mt][nt], ah[mt], bl);
                    mma16816(acc[mt][nt], al[mt], bh);
                }
            }
        }
        __syncthreads();
    }

    // ---- epilogue ----
#pragma unroll
    for (int mt = 0; mt < 2; mt++) {
#pragma unroll
        for (int half = 0; half < 2; half++) {
            int row = m0 + wm * 32 + mt * 16 + gid + half * 8;
            if (row >= M) continue;
            float* cp = C + (size_t)row * N + n0 + wn * 64;
#pragma unroll
            for (int nt = 0; nt < 8; nt++) {
                int col = nt * 8 + tq * 2;
                float v0 = acc[mt][nt][half * 2 + 0];
                float v1 = acc[mt][nt][half * 2 + 1];
                if (HAS_BIAS) {
                    const float* bp = bias + n0 + wn * 64 + col;
                    v0 += bp[0]; v1 += bp[1];
                }
                if (RELU) { v0 = fmaxf(v0, 0.f); v1 = fmaxf(v1, 0.f); }
                *reinterpret_cast<float2*>(cp + col) = make_float2(v0, v1);
            }
        }
    }
}

// ---------------------------------------------------------------------------
// FFMA SGEMM (kept for L1, K=32)
// ---------------------------------------------------------------------------
template<bool RELU_OUT, bool HAS_BIAS>
__global__ __launch_bounds__(256)
void k_sgemm(const float* __restrict__ A, const float* __restrict__ B,
             const float* __restrict__ bias, float* __restrict__ C,
             int M, int K, int N) {
    constexpr int BM = 128, BN = 128, BK = 8, TM = 8, TN = 8;
    __shared__ float As[BK][BM];
    __shared__ float Bs[BK][BN];
    int tid = threadIdx.x;
    int tr = tid / 16, tc = tid % 16;
    float acc[TM][TN];
#pragma unroll
    for (int i = 0; i < TM; i++)
#pragma unroll
        for (int j = 0; j < TN; j++) acc[i][j] = 0.f;
    int aRow = tid >> 1, aCol = (tid & 1) << 2;
    int bRow = tid >> 5, bCol = (tid & 31) << 2;
    long long aGRow = (long long)blockIdx.y * BM + aRow;
    const bool aValid = aGRow < M;
    const float* Aptr = A + aGRow * (long long)K + aCol;
    const float* Bptr = B + (long long)bRow * N + (long long)blockIdx.x * BN + bCol;
    for (int k0 = 0; k0 < K; k0 += BK) {
        float4 av = make_float4(0.f, 0.f, 0.f, 0.f);
        if (aValid) av = *reinterpret_cast<const float4*>(Aptr + k0);
        As[aCol + 0][aRow] = av.x; As[aCol + 1][aRow] = av.y;
        As[aCol + 2][aRow] = av.z; As[aCol + 3][aRow] = av.w;
        float4 bv = *reinterpret_cast<const float4*>(Bptr + (long long)k0 * N);
        *reinterpret_cast<float4*>(&Bs[bRow][bCol]) = bv;
        __syncthreads();
#pragma unroll
        for (int k = 0; k < BK; k++) {
            float rm[TM], rn[TN];
#pragma unroll
            for (int i = 0; i < TM; i++) rm[i] = As[k][tr * TM + i];
#pragma unroll
            for (int j = 0; j < TN; j++) rn[j] = Bs[k][tc * TN + j];
#pragma unroll
            for (int i = 0; i < TM; i++)
#pragma unroll
                for (int j = 0; j < TN; j++) acc[i][j] += rm[i] * rn[j];
        }
        __syncthreads();
    }
#pragma unroll
    for (int i = 0; i < TM; i++) {
        long long row = (long long)blockIdx.y * BM + tr * TM + i;
        if (row >= M) continue;
#pragma unroll
        for (int j = 0; j < TN; j += 4) {
            int col = blockIdx.x * BN + tc * TN + j;
            float4 v = make_float4(acc[i][j], acc[i][j + 1], acc[i][j + 2], acc[i][j + 3]);
            if (HAS_BIAS) {
                float4 bb = *reinterpret_cast<const float4*>(bias + col);
                v.x += bb.x; v.y += bb.y; v.z += bb.z; v.w += bb.w;
            }
            if (RELU_OUT) {
                v.x = fmaxf(v.x, 0.f); v.y = fmaxf(v.y, 0.f);
                v.z = fmaxf(v.z, 0.f); v.w = fmaxf(v.w, 0.f);
            }
            *reinterpret_cast<float4*>(C + row * (long long)N + col) = v;
        }
    }
}

// ---------------------------------------------------------------------------
// L5 small kernels
// ---------------------------------------------------------------------------
__global__ void k_gemm_relu_256x6(const float* __restrict__ A, const float* __restrict__ W,
                                  float* __restrict__ C, int M) {
    __shared__ float Ws[256 * 6];
    for (int i = threadIdx.x; i < 256 * 6; i += blockDim.x) Ws[i] = W[i];
    __syncthreads();
    int warp = threadIdx.x >> 5, lane = threadIdx.x & 31;
    long long row = (long long)blockIdx.x * 8 + warp;
    if (row >= M) return;
    float a0 = 0.f, a1 = 0.f, a2 = 0.f, a3 = 0.f, a4 = 0.f, a5 = 0.f;
    const float* a = A + row * 256;
#pragma unroll
    for (int k0 = 0; k0 < 256; k0 += 32) {
        float av = fmaxf(a[k0 + lane], 0.f);
        const float* w = &Ws[(k0 + lane) * 6];
        a0 += av * w[0]; a1 += av * w[1]; a2 += av * w[2];
        a3 += av * w[3]; a4 += av * w[4]; a5 += av * w[5];
    }
#pragma unroll
    for (int off = 16; off > 0; off >>= 1) {
        a0 += __shfl_down_sync(0xffffffffu, a0, off);
        a1 += __shfl_down_sync(0xffffffffu, a1, off);
        a2 += __shfl_down_sync(0xffffffffu, a2, off);
        a3 += __shfl_down_sync(0xffffffffu, a3, off);
        a4 += __shfl_down_sync(0xffffffffu, a4, off);
        a5 += __shfl_down_sync(0xffffffffu, a5, off);
    }
    if (lane == 0) {
        float* c = C + row * 6;
        c[0] = a0; c[1] = a1; c[2] = a2; c[3] = a3; c[4] = a4; c[5] = a5;
    }
}

__global__ void k_selfinit6(const float* __restrict__ z, float* __restrict__ out,
                            const float* __restrict__ dinv, const float* __restrict__ b, int n) {
    int i = blockIdx.x * blockDim.x + threadIdx.x;
    if (i >= n * 6) return;
    int node = i / 6, c = i - node * 6;
    float dv = dinv[node];
    out[i] = z[i] * dv * dv + b[c];
}

__global__ void k_agg6(const float* __restrict__ z, float* __restrict__ out,
                       const void* __restrict__ ei, const float* __restrict__ dinv, int E) {
    int e = blockIdx.x * blockDim.x + threadIdx.x;
    if (e >= E) return;
    int s, d; edge_get(ei, E, e, s, d);
    float nrm = dinv[s] * dinv[d];
    const float* zp = z + (long long)s * 6;
    float* op = out + (long long)d * 6;
#pragma unroll
    for (int j = 0; j < 6; j++) atomicAdd(&op[j], zp[j] * nrm);
}

// ---------------------------------------------------------------------------

static inline unsigned cdiv(long long a, long long b) { return (unsigned)((a + b - 1) / b); }

extern "C" void kernel_launch(void* const* d_in, const int* in_sizes, int n_in,
                              void* d_out, int out_size) {
    const float* x  = (const float*)d_in[0];
    const void*  ei = d_in[1];
    const float* W1 = (const float*)d_in[2];  const float* b1 = (const float*)d_in[3];
    const float* W2 = (const float*)d_in[4];  const float* b2 = (const float*)d_in[5];
    const float* W3 = (const float*)d_in[6];  const float* b3 = (const float*)d_in[7];
    const float* W4 = (const float*)d_in[8];  const float* b4 = (const float*)d_in[9];
    const float* W5 = (const float*)d_in[10]; const float* b5 = (const float*)d_in[11];

    int N = in_sizes[0] / 32;
    int E = in_sizes[1] / 2;
    float* out = (float*)d_out;

    float *bufA, *bufB, *z6, *deg, *dinv;
    __nv_bfloat16 *Ahi, *Alo, *W2h, *W2l, *W3h, *W3l, *W4h, *W4l;
    cudaGetSymbolAddress((void**)&bufA, g_bufA);
    cudaGetSymbolAddress((void**)&bufB, g_bufB);
    cudaGetSymbolAddress((void**)&z6,   g_z6);
    cudaGetSymbolAddress((void**)&deg,  g_deg);
    cudaGetSymbolAddress((void**)&dinv, g_dinv);
    cudaGetSymbolAddress((void**)&Ahi,  g_Ahi);
    cudaGetSymbolAddress((void**)&Alo,  g_Alo);
    cudaGetSymbolAddress((void**)&W2h,  g_W2h); cudaGetSymbolAddress((void**)&W2l, g_W2l);
    cudaGetSymbolAddress((void**)&W3h,  g_W3h); cudaGetSymbolAddress((void**)&W3l, g_W3l);
    cudaGetSymbolAddress((void**)&W4h,  g_W4h); cudaGetSymbolAddress((void**)&W4l, g_W4l);

    const int SMEM_DYN = 2 * STG_STRIDE * 2;   // 2 stages * 20480 bf16 = 81920 B
    cudaFuncSetAttribute((const void*)k_mma<true, true>,   cudaFuncAttributeMaxDynamicSharedMemorySize, SMEM_DYN);
    cudaFuncSetAttribute((const void*)k_mma<false, false>, cudaFuncAttributeMaxDynamicSharedMemorySize, SMEM_DYN);

    // --- edge dtype + normalization ---
    int npairs = (2 * E < 8192) ? E : 4096;
    k_detect<<<1, 256>>>((const unsigned*)ei, npairs);
    k_zero<<<cdiv(N, 256), 256>>>(deg, N);
    k_deg<<<cdiv(E, 256), 256>>>(ei, deg, E);
    k_dinv<<<cdiv(N, 256), 256>>>(deg, dinv, N);

    // --- weight transposes + splits (tiny) ---
    k_wsplit<<<cdiv(256 * 1024, 256), 256>>>(W2, W2h, W2l, 256, 1024);
    k_wsplit<<<cdiv(1024 * 1024, 256), 256>>>(W3, W3h, W3l, 1024, 1024);
    k_wsplit<<<cdiv(1024 * 256, 256), 256>>>(W4, W4h, W4l, 1024, 256);

    // --- L1: t = A*x (F=32); h1 = relu(t@W1+b1) -> bufB [N,256] (FFMA) ---
    k_selfinit<32><<<cdiv((long long)N * 8, 256), 256>>>(x, bufA, dinv, nullptr, N);
    k_agg<8><<<cdiv(E, 32), 256>>>(x, bufA, ei, dinv, E);
    k_sgemm<true, true><<<dim3(2, cdiv(N, 128)), 256>>>(bufA, W1, b1, bufB, N, 32, 256);

    // --- L2: t = A*h1 (F=256) -> bufA; h2 = relu(t@W2+b2) -> bufB [N,1024] ---
    k_selfinit<256><<<cdiv((long long)N * 64, 256), 256>>>(bufB, bufA, dinv, nullptr, N);
    k_agg<64><<<cdiv(E, 4), 256>>>(bufB, bufA, ei, dinv, E);
    k_asplit<<<cdiv((long long)N * 64, 256), 256>>>(bufA, Ahi, Alo, (long long)N * 64);
    k_mma<true, true><<<dim3(8, cdiv(N, 128)), 256, SMEM_DYN>>>(Ahi, Alo, W2h, W2l, b2, bufB, N, 256, 1024);

    // --- L3: t = A*h2 (F=1024) -> bufA; h3 = relu(t@W3+b3) -> bufB [N,1024] ---
    k_selfinit<1024><<<cdiv((long long)N * 256, 256), 256>>>(bufB, bufA, dinv, nullptr, N);
    k_agg<256><<<cdiv(E, 1), 256>>>(bufB, bufA, ei, dinv, E);
    k_asplit<<<cdiv((long long)N * 256, 256), 256>>>(bufA, Ahi, Alo, (long long)N * 256);
    k_mma<true, true><<<dim3(8, cdiv(N, 128)), 256, SMEM_DYN>>>(Ahi, Alo, W3h, W3l, b3, bufB, N, 1024, 1024);

    // --- L4 (transform-first): z = h3@W4 -> bufA [N,256]; t = A*z + b4 -> bufB ---
    k_asplit<<<cdiv((long long)N * 256, 256), 256>>>(bufB, Ahi, Alo, (long long)N * 256);
    k_mma<false, false><<<dim3(2, cdiv(N, 128)), 256, SMEM_DYN>>>(Ahi, Alo, W4h, W4l, nullptr, bufA, N, 1024, 256);
    k_selfinit<256><<<cdiv((long long)N * 64, 256), 256>>>(bufA, bufB, dinv, b4, N);
    k_agg<64><<<cdiv(E, 4), 256>>>(bufA, bufB, ei, dinv, E);

    // --- L5: z6 = relu(bufB)@W5; out = A*z6 + b5 ---
    k_gemm_relu_256x6<<<cdiv(N, 8), 256>>>(bufB, W5, z6, N);
    k_selfinit6<<<cdiv((long long)N * 6, 256), 256>>>(z6, out, dinv, b5, N);
    k_agg6<<<cdiv(E, 256), 256>>>(z6, out, ei, dinv, E);
}

// round 8
// speedup vs baseline: 2.6389x; 1.9731x over previous
#include <cuda_runtime.h>
#include <cuda_bf16.h>
#include <cstdint>

// ---------------------------------------------------------------------------
// GCN5: 5-layer GCN, N=100000, E=3.2M, dims 32->256->1024->1024->256->6
// R7: CSR pull-mode aggregation (no float atomics), mma.sync bf16 GEMMs.
// ---------------------------------------------------------------------------

__device__ float g_bufA[102400000];   // 100000 * 1024
__device__ float g_bufB[102400000];   // 100000 * 1024
__device__ float g_z6[600064];
__device__ float g_dinv[100000];
__device__ int   g_is64;

__device__ int g_cnt[100000];
__device__ int g_rowptr[100001];
__device__ int g_next[100000];
__device__ int g_csr[3300000];
__device__ int g_bsum[512];

__device__ __align__(128) __nv_bfloat16 g_Ahi[102400000];
__device__ __align__(128) __nv_bfloat16 g_Alo[102400000];
__device__ __align__(128) __nv_bfloat16 g_W2h[262144], g_W2l[262144];
__device__ __align__(128) __nv_bfloat16 g_W3h[1048576], g_W3l[1048576];
__device__ __align__(128) __nv_bfloat16 g_W4h[262144], g_W4l[262144];

// ---------------------------------------------------------------------------
// edge dtype detection
// ---------------------------------------------------------------------------
__global__ void k_detect(const unsigned* __restrict__ w, int npairs) {
    __shared__ int any;
    if (threadIdx.x == 0) any = 0;
    __syncthreads();
    for (int i = threadIdx.x; i < npairs; i += blockDim.x)
        if (w[2 * i + 1] != 0u) any = 1;
    __syncthreads();
    if (threadIdx.x == 0) g_is64 = (any == 0) ? 1 : 0;
}

__device__ __forceinline__ void edge_get(const void* ei, int E, int e, int& s, int& d) {
    if (g_is64) {
        const long long* p = (const long long*)ei;
        s = (int)p[e]; d = (int)p[E + e];
    } else {
        const int* p = (const int*)ei;
        s = p[e]; d = p[E + e];
    }
}

// ---------------------------------------------------------------------------
// CSR build
// ---------------------------------------------------------------------------
__global__ void k_zeroi(int* __restrict__ p, int n) {
    int i = blockIdx.x * blockDim.x + threadIdx.x;
    if (i < n) p[i] = 0;
}
__global__ void k_count(const void* __restrict__ ei, int* __restrict__ cnt, int E) {
    int e = blockIdx.x * blockDim.x + threadIdx.x;
    if (e >= E) return;
    int s, d; edge_get(ei, E, e, s, d);
    atomicAdd(&cnt[d], 1);
}
// per-256-block exclusive scan + block sums
__global__ void k_scan1(const int* __restrict__ cnt, int* __restrict__ pre,
                        int* __restrict__ bsum, int n) {
    __shared__ int sm[256];
    int i = blockIdx.x * 256 + threadIdx.x;
    int v = (i < n) ? cnt[i] : 0;
    sm[threadIdx.x] = v;
    __syncthreads();
    for (int off = 1; off < 256; off <<= 1) {
        int t = (threadIdx.x >= off) ? sm[threadIdx.x - off] : 0;
        __syncthreads();
        sm[threadIdx.x] += t;
        __syncthreads();
    }
    if (i < n) pre[i] = sm[threadIdx.x] - v;
    if (threadIdx.x == 255) bsum[blockIdx.x] = sm[255];
}
__global__ void k_scan2(int* __restrict__ bsum, int nb) {
    __shared__ int sm[512];
    int v = (threadIdx.x < nb) ? bsum[threadIdx.x] : 0;
    sm[threadIdx.x] = v;
    __syncthreads();
    for (int off = 1; off < 512; off <<= 1) {
        int t = (threadIdx.x >= off) ? sm[threadIdx.x - off] : 0;
        __syncthreads();
        sm[threadIdx.x] += t;
        __syncthreads();
    }
    if (threadIdx.x < nb) bsum[threadIdx.x] = sm[threadIdx.x] - v;
}
__global__ void k_scan3(int* __restrict__ pre, const int* __restrict__ bsum, int n, int E) {
    int i = blockIdx.x * 256 + threadIdx.x;
    if (i < n) pre[i] += bsum[blockIdx.x];
    if (i == 0) pre[n] = E;
}
__global__ void k_dinv2(const int* __restrict__ cnt, float* __restrict__ dinv, int n) {
    int i = blockIdx.x * blockDim.x + threadIdx.x;
    if (i < n) dinv[i] = rsqrtf((float)cnt[i] + 1.0f);
}
__global__ void k_copy(int* __restrict__ dst, const int* __restrict__ src, int n) {
    int i = blockIdx.x * blockDim.x + threadIdx.x;
    if (i < n) dst[i] = src[i];
}
__global__ void k_fill(const void* __restrict__ ei, int* __restrict__ next,
                       int* __restrict__ csr, int E) {
    int e = blockIdx.x * blockDim.x + threadIdx.x;
    if (e >= E) return;
    int s, d; edge_get(ei, E, e, s, d);
    int pos = atomicAdd(&next[d], 1);
    csr[pos] = s;
}

// ---------------------------------------------------------------------------
// CSR pull aggregation: out[d] = dinv[d]*(sum_in dinv[s]*h[s] + dinv[d]*h[d]) + bias
// F4 = float4s per row (8 / 64 / 256). Threads-per-node = F4.
// ---------------------------------------------------------------------------
template<int F4>
__global__ __launch_bounds__(256)
void k_csragg(const float* __restrict__ h, float* __restrict__ out,
              const int* __restrict__ rowptr, const int* __restrict__ csr,
              const float* __restrict__ dinv, const float* __restrict__ bias, int n) {
    constexpr int NPB = 256 / F4;
    int node = blockIdx.x * NPB + threadIdx.x / F4;
    int lane = threadIdx.x % F4;
    if (node >= n) return;
    int beg = __ldg(&rowptr[node]);
    int end = __ldg(&rowptr[node + 1]);
    const float4* h4 = reinterpret_cast<const float4*>(h);
    float4 acc = make_float4(0.f, 0.f, 0.f, 0.f);
#pragma unroll 4
    for (int j = beg; j < end; j++) {
        int s = __ldg(&csr[j]);
        float w = __ldg(&dinv[s]);
        float4 v = __ldg(&h4[(long long)s * F4 + lane]);
        acc.x += w * v.x; acc.y += w * v.y; acc.z += w * v.z; acc.w += w * v.w;
    }
    float dn = dinv[node];
    float4 hv = __ldg(&h4[(long long)node * F4 + lane]);
    acc.x = (acc.x + dn * hv.x) * dn;
    acc.y = (acc.y + dn * hv.y) * dn;
    acc.z = (acc.z + dn * hv.z) * dn;
    acc.w = (acc.w + dn * hv.w) * dn;
    if (bias) {
        float4 b = reinterpret_cast<const float4*>(bias)[lane];
        acc.x += b.x; acc.y += b.y; acc.z += b.z; acc.w += b.w;
    }
    reinterpret_cast<float4*>(out)[(long long)node * F4 + lane] = acc;
}

// F=6 variant (8 threads per node, 6 active lanes)
__global__ __launch_bounds__(256)
void k_csragg6(const float* __restrict__ z, float* __restrict__ out,
               const int* __restrict__ rowptr, const int* __restrict__ csr,
               const float* __restrict__ dinv, const float* __restrict__ bias, int n) {
    int node = blockIdx.x * 32 + threadIdx.x / 8;
    int lane = threadIdx.x % 8;
    if (node >= n) return;
    int beg = __ldg(&rowptr[node]);
    int end = __ldg(&rowptr[node + 1]);
    float acc = 0.f;
    for (int j = beg; j < end; j++) {
        int s = __ldg(&csr[j]);
        if (lane < 6) acc += __ldg(&dinv[s]) * __ldg(&z[(long long)s * 6 + lane]);
    }
    float dn = dinv[node];
    if (lane < 6)
        out[(long long)node * 6 + lane] =
            (acc + dn * __ldg(&z[(long long)node * 6 + lane])) * dn + bias[lane];
}

// ---------------------------------------------------------------------------
// fp32 -> bf16 hi/lo splits
// ---------------------------------------------------------------------------
__global__ void k_asplit(const float* __restrict__ x, __nv_bfloat16* __restrict__ hi,
                         __nv_bfloat16* __restrict__ lo, long long n4) {
    long long i = blockIdx.x * (long long)blockDim.x + threadIdx.x;
    if (i >= n4) return;
    float4 v = reinterpret_cast<const float4*>(x)[i];
    __nv_bfloat16 h0 = __float2bfloat16_rn(v.x), h1 = __float2bfloat16_rn(v.y);
    __nv_bfloat16 h2 = __float2bfloat16_rn(v.z), h3 = __float2bfloat16_rn(v.w);
    __nv_bfloat16 l0 = __float2bfloat16_rn(v.x - __bfloat162float(h0));
    __nv_bfloat16 l1 = __float2bfloat16_rn(v.y - __bfloat162float(h1));
    __nv_bfloat16 l2 = __float2bfloat16_rn(v.z - __bfloat162float(h2));
    __nv_bfloat16 l3 = __float2bfloat16_rn(v.w - __bfloat162float(h3));
    reinterpret_cast<__nv_bfloat162*>(hi)[2 * i]     = __nv_bfloat162(h0, h1);
    reinterpret_cast<__nv_bfloat162*>(hi)[2 * i + 1] = __nv_bfloat162(h2, h3);
    reinterpret_cast<__nv_bfloat162*>(lo)[2 * i]     = __nv_bfloat162(l0, l1);
    reinterpret_cast<__nv_bfloat162*>(lo)[2 * i + 1] = __nv_bfloat162(l2, l3);
}

// W[K,N] -> Wt_hi/lo[N,K]
__global__ void k_wsplit(const float* __restrict__ W, __nv_bfloat16* __restrict__ th,
                         __nv_bfloat16* __restrict__ tl, int K, int N) {
    int i = blockIdx.x * blockDim.x + threadIdx.x;
    if (i >= K * N) return;
    int k = i / N, n = i - k * N;
    float w = W[i];
    __nv_bfloat16 h = __float2bfloat16_rn(w);
    __nv_bfloat16 l = __float2bfloat16_rn(w - __bfloat162float(h));
    th[(long long)n * K + k] = h;
    tl[(long long)n * K + k] = l;
}

// ---------------------------------------------------------------------------
// mma.sync bf16 GEMM (3-term fp32 split), 128x128x32 tile, cp.async 2-stage
// ---------------------------------------------------------------------------
__device__ __forceinline__ uint32_t smem_u32(const void* p) {
    uint32_t a;
    asm("{ .reg .u64 t; cvta.to.shared.u64 t, %1; cvt.u32.u64 %0, t; }" : "=r"(a) : "l"(p));
    return a;
}
__device__ __forceinline__ void cp16(uint32_t dst, const void* src, bool v) {
    asm volatile("cp.async.cg.shared.global [%0], [%1], 16, %2;"
                 :: "r"(dst), "l"(src), "r"(v ? 16 : 0) : "memory");
}
__device__ __forceinline__ uint32_t lds32(const __nv_bfloat16* p) {
    return *reinterpret_cast<const uint32_t*>(p);
}
__device__ __forceinline__ void mma16816(float* c, const uint32_t* a, const uint32_t* b) {
    asm volatile("mma.sync.aligned.m16n8k16.row.col.f32.bf16.bf16.f32 "
                 "{%0,%1,%2,%3}, {%4,%5,%6,%7}, {%8,%9}, {%0,%1,%2,%3};"
                 : "+f"(c[0]), "+f"(c[1]), "+f"(c[2]), "+f"(c[3])
                 : "r"(a[0]), "r"(a[1]), "r"(a[2]), "r"(a[3]), "r"(b[0]), "r"(b[1]));
}

#define STG_STRIDE 20480
#define ROW_ST 40

template<bool RELU, bool HAS_BIAS>
__global__ __launch_bounds__(256)
void k_mma(const __nv_bfloat16* __restrict__ Ah, const __nv_bfloat16* __restrict__ Al,
           const __nv_bfloat16* __restrict__ Bh, const __nv_bfloat16* __restrict__ Bl,
           const float* __restrict__ bias, float* __restrict__ C,
           int M, int K, int N) {
    extern __shared__ __align__(16) __nv_bfloat16 sm[];
    const int tid = threadIdx.x;
    const int wid = tid >> 5, lane = tid & 31;
    const int wm = wid & 3, wn = wid >> 2;
    const int gid = lane >> 2, tq = lane & 3;
    const int m0 = blockIdx.y * 128, n0 = blockIdx.x * 128;

    float acc[2][8][4];
#pragma unroll
    for (int a = 0; a < 2; a++)
#pragma unroll
        for (int b = 0; b < 8; b++)
#pragma unroll
            for (int c = 0; c < 4; c++) acc[a][b][c] = 0.f;

    const int nK = K >> 5;

    auto issue = [&](int it, int s) {
        int k0 = it << 5;
#pragma unroll
        for (int i = 0; i < 2; i++) {
            int idx = tid + i * 256;
            int row = idx >> 2, g = idx & 3;
            uint32_t so = (uint32_t)s * STG_STRIDE + row * ROW_ST + g * 8;
            bool av = (m0 + row) < M;
            size_t gA = (size_t)(m0 + row) * K + k0 + g * 8;
            cp16(smem_u32(sm + so),          Ah + (av ? gA : 0), av);
            cp16(smem_u32(sm + so + 5120),   Al + (av ? gA : 0), av);
            size_t gB = (size_t)(n0 + row) * K + k0 + g * 8;
            cp16(smem_u32(sm + so + 10240),  Bh + gB, true);
            cp16(smem_u32(sm + so + 15360),  Bl + gB, true);
        }
        asm volatile("cp.async.commit_group;" ::: "memory");
    };

    issue(0, 0);
    for (int it = 0; it < nK; ++it) {
        if (it + 1 < nK) {
            issue(it + 1, (it + 1) & 1);
            asm volatile("cp.async.wait_group 1;" ::: "memory");
        } else {
            asm volatile("cp.async.wait_group 0;" ::: "memory");
        }
        __syncthreads();

        const __nv_bfloat16* sbase = sm + (uint32_t)(it & 1) * STG_STRIDE;
#pragma unroll
        for (int kk = 0; kk < 32; kk += 16) {
            uint32_t ah[2][4], al[2][4];
#pragma unroll
            for (int mt = 0; mt < 2; mt++) {
                const __nv_bfloat16* p = sbase + (wm * 32 + mt * 16 + gid) * ROW_ST + kk + tq * 2;
                ah[mt][0] = lds32(p);
                ah[mt][1] = lds32(p + 8 * ROW_ST);
                ah[mt][2] = lds32(p + 8);
                ah[mt][3] = lds32(p + 8 * ROW_ST + 8);
                al[mt][0] = lds32(p + 5120);
                al[mt][1] = lds32(p + 5120 + 8 * ROW_ST);
                al[mt][2] = lds32(p + 5120 + 8);
                al[mt][3] = lds32(p + 5120 + 8 * ROW_ST + 8);
            }
#pragma unroll
            for (int nt = 0; nt < 8; nt++) {
                const __nv_bfloat16* q = sbase + 10240 + (wn * 64 + nt * 8 + gid) * ROW_ST + kk + tq * 2;
                uint32_t bh[2] = { lds32(q), lds32(q + 8) };
                uint32_t bl[2] = { lds32(q + 5120), lds32(q + 5120 + 8) };
#pragma unroll
                for (int mt = 0; mt < 2; mt++) {
                    mma16816(acc[mt][nt], ah[mt], bh);
                    mma16816(acc[mt][nt], ah[mt], bl);
                    mma16816(acc[mt][nt], al[mt], bh);
                }
            }
        }
        __syncthreads();
    }

#pragma unroll
    for (int mt = 0; mt < 2; mt++) {
#pragma unroll
        for (int half = 0; half < 2; half++) {
            int row = m0 + wm * 32 + mt * 16 + gid + half * 8;
            if (row >= M) continue;
            float* cp = C + (size_t)row * N + n0 + wn * 64;
#pragma unroll
            for (int nt = 0; nt < 8; nt++) {
                int col = nt * 8 + tq * 2;
                float v0 = acc[mt][nt][half * 2 + 0];
                float v1 = acc[mt][nt][half * 2 + 1];
                if (HAS_BIAS) {
                    const float* bp = bias + n0 + wn * 64 + col;
                    v0 += bp[0]; v1 += bp[1];
                }
                if (RELU) { v0 = fmaxf(v0, 0.f); v1 = fmaxf(v1, 0.f); }
                *reinterpret_cast<float2*>(cp + col) = make_float2(v0, v1);
            }
        }
    }
}

// ---------------------------------------------------------------------------
// FFMA SGEMM (L1, K=32)
// ---------------------------------------------------------------------------
template<bool RELU_OUT, bool HAS_BIAS>
__global__ __launch_bounds__(256)
void k_sgemm(const float* __restrict__ A, const float* __restrict__ B,
             const float* __restrict__ bias, float* __restrict__ C,
             int M, int K, int N) {
    constexpr int BM = 128, BN = 128, BK = 8, TM = 8, TN = 8;
    __shared__ float As[BK][BM];
    __shared__ float Bs[BK][BN];
    int tid = threadIdx.x;
    int tr = tid / 16, tc = tid % 16;
    float acc[TM][TN];
#pragma unroll
    for (int i = 0; i < TM; i++)
#pragma unroll
        for (int j = 0; j < TN; j++) acc[i][j] = 0.f;
    int aRow = tid >> 1, aCol = (tid & 1) << 2;
    int bRow = tid >> 5, bCol = (tid & 31) << 2;
    long long aGRow = (long long)blockIdx.y * BM + aRow;
    const bool aValid = aGRow < M;
    const float* Aptr = A + aGRow * (long long)K + aCol;
    const float* Bptr = B + (long long)bRow * N + (long long)blockIdx.x * BN + bCol;
    for (int k0 = 0; k0 < K; k0 += BK) {
        float4 av = make_float4(0.f, 0.f, 0.f, 0.f);
        if (aValid) av = *reinterpret_cast<const float4*>(Aptr + k0);
        As[aCol + 0][aRow] = av.x; As[aCol + 1][aRow] = av.y;
        As[aCol + 2][aRow] = av.z; As[aCol + 3][aRow] = av.w;
        float4 bv = *reinterpret_cast<const float4*>(Bptr + (long long)k0 * N);
        *reinterpret_cast<float4*>(&Bs[bRow][bCol]) = bv;
        __syncthreads();
#pragma unroll
        for (int k = 0; k < BK; k++) {
            float rm[TM], rn[TN];
#pragma unroll
            for (int i = 0; i < TM; i++) rm[i] = As[k][tr * TM + i];
#pragma unroll
            for (int j = 0; j < TN; j++) rn[j] = Bs[k][tc * TN + j];
#pragma unroll
            for (int i = 0; i < TM; i++)
#pragma unroll
                for (int j = 0; j < TN; j++) acc[i][j] += rm[i] * rn[j];
        }
        __syncthreads();
    }
#pragma unroll
    for (int i = 0; i < TM; i++) {
        long long row = (long long)blockIdx.y * BM + tr * TM + i;
        if (row >= M) continue;
#pragma unroll
        for (int j = 0; j < TN; j += 4) {
            int col = blockIdx.x * BN + tc * TN + j;
            float4 v = make_float4(acc[i][j], acc[i][j + 1], acc[i][j + 2], acc[i][j + 3]);
            if (HAS_BIAS) {
                float4 bb = *reinterpret_cast<const float4*>(bias + col);
                v.x += bb.x; v.y += bb.y; v.z += bb.z; v.w += bb.w;
            }
            if (RELU_OUT) {
                v.x = fmaxf(v.x, 0.f); v.y = fmaxf(v.y, 0.f);
                v.z = fmaxf(v.z, 0.f); v.w = fmaxf(v.w, 0.f);
            }
            *reinterpret_cast<float4*>(C + row * (long long)N + col) = v;
        }
    }
}

// ---------------------------------------------------------------------------
// L5: z = relu(A[M,256]) @ W[256,6]
// ---------------------------------------------------------------------------
__global__ void k_gemm_relu_256x6(const float* __restrict__ A, const float* __restrict__ W,
                                  float* __restrict__ C, int M) {
    __shared__ float Ws[256 * 6];
    for (int i = threadIdx.x; i < 256 * 6; i += blockDim.x) Ws[i] = W[i];
    __syncthreads();
    int warp = threadIdx.x >> 5, lane = threadIdx.x & 31;
    long long row = (long long)blockIdx.x * 8 + warp;
    if (row >= M) return;
    float a0 = 0.f, a1 = 0.f, a2 = 0.f, a3 = 0.f, a4 = 0.f, a5 = 0.f;
    const float* a = A + row * 256;
#pragma unroll
    for (int k0 = 0; k0 < 256; k0 += 32) {
        float av = fmaxf(a[k0 + lane], 0.f);
        const float* w = &Ws[(k0 + lane) * 6];
        a0 += av * w[0]; a1 += av * w[1]; a2 += av * w[2];
        a3 += av * w[3]; a4 += av * w[4]; a5 += av * w[5];
    }
#pragma unroll
    for (int off = 16; off > 0; off >>= 1) {
        a0 += __shfl_down_sync(0xffffffffu, a0, off);
        a1 += __shfl_down_sync(0xffffffffu, a1, off);
        a2 += __shfl_down_sync(0xffffffffu, a2, off);
        a3 += __shfl_down_sync(0xffffffffu, a3, off);
        a4 += __shfl_down_sync(0xffffffffu, a4, off);
        a5 += __shfl_down_sync(0xffffffffu, a5, off);
    }
    if (lane == 0) {
        float* c = C + row * 6;
        c[0] = a0; c[1] = a1; c[2] = a2; c[3] = a3; c[4] = a4; c[5] = a5;
    }
}

// ---------------------------------------------------------------------------

static inline unsigned cdiv(long long a, long long b) { return (unsigned)((a + b - 1) / b); }

extern "C" void kernel_launch(void* const* d_in, const int* in_sizes, int n_in,
                              void* d_out, int out_size) {
    const float* x  = (const float*)d_in[0];
    const void*  ei = d_in[1];
    const float* W1 = (const float*)d_in[2];  const float* b1 = (const float*)d_in[3];
    const float* W2 = (const float*)d_in[4];  const float* b2 = (const float*)d_in[5];
    const float* W3 = (const float*)d_in[6];  const float* b3 = (const float*)d_in[7];
    const float* W4 = (const float*)d_in[8];  const float* b4 = (const float*)d_in[9];
    const float* W5 = (const float*)d_in[10]; const float* b5 = (const float*)d_in[11];

    int N = in_sizes[0] / 32;
    int E = in_sizes[1] / 2;
    float* out = (float*)d_out;

    float *bufA, *bufB, *z6, *dinv;
    int *cnt, *rowptr, *nxt, *csr, *bsum;
    __nv_bfloat16 *Ahi, *Alo, *W2h, *W2l, *W3h, *W3l, *W4h, *W4l;
    cudaGetSymbolAddress((void**)&bufA, g_bufA);
    cudaGetSymbolAddress((void**)&bufB, g_bufB);
    cudaGetSymbolAddress((void**)&z6,   g_z6);
    cudaGetSymbolAddress((void**)&dinv, g_dinv);
    cudaGetSymbolAddress((void**)&cnt,    g_cnt);
    cudaGetSymbolAddress((void**)&rowptr, g_rowptr);
    cudaGetSymbolAddress((void**)&nxt,    g_next);
    cudaGetSymbolAddress((void**)&csr,    g_csr);
    cudaGetSymbolAddress((void**)&bsum,   g_bsum);
    cudaGetSymbolAddress((void**)&Ahi,  g_Ahi);
    cudaGetSymbolAddress((void**)&Alo,  g_Alo);
    cudaGetSymbolAddress((void**)&W2h,  g_W2h); cudaGetSymbolAddress((void**)&W2l, g_W2l);
    cudaGetSymbolAddress((void**)&W3h,  g_W3h); cudaGetSymbolAddress((void**)&W3l, g_W3l);
    cudaGetSymbolAddress((void**)&W4h,  g_W4h); cudaGetSymbolAddress((void**)&W4l, g_W4l);

    const int SMEM_DYN = 2 * STG_STRIDE * 2;   // 81920 B
    cudaFuncSetAttribute((const void*)k_mma<true, true>,   cudaFuncAttributeMaxDynamicSharedMemorySize, SMEM_DYN);
    cudaFuncSetAttribute((const void*)k_mma<false, false>, cudaFuncAttributeMaxDynamicSharedMemorySize, SMEM_DYN);

    // --- edge dtype + CSR build ---
    int npairs = (2 * E < 8192) ? E : 4096;
    k_detect<<<1, 256>>>((const unsigned*)ei, npairs);
    k_zeroi<<<cdiv(N, 256), 256>>>(cnt, N);
    k_count<<<cdiv(E, 256), 256>>>(ei, cnt, E);
    int nb = cdiv(N, 256);
    k_scan1<<<nb, 256>>>(cnt, rowptr, bsum, N);
    k_scan2<<<1, 512>>>(bsum, nb);
    k_scan3<<<nb, 256>>>(rowptr, bsum, N, E);
    k_dinv2<<<cdiv(N, 256), 256>>>(cnt, dinv, N);
    k_copy<<<cdiv(N, 256), 256>>>(nxt, rowptr, N);
    k_fill<<<cdiv(E, 256), 256>>>(ei, nxt, csr, E);

    // --- weight transposes + splits ---
    k_wsplit<<<cdiv(256 * 1024, 256), 256>>>(W2, W2h, W2l, 256, 1024);
    k_wsplit<<<cdiv(1024 * 1024, 256), 256>>>(W3, W3h, W3l, 1024, 1024);
    k_wsplit<<<cdiv(1024 * 256, 256), 256>>>(W4, W4h, W4l, 1024, 256);

    // --- L1: t = A*x (F=32) -> bufA ; h1 = relu(t@W1+b1) -> bufB [N,256] ---
    k_csragg<8><<<cdiv(N, 32), 256>>>(x, bufA, rowptr, csr, dinv, nullptr, N);
    k_sgemm<true, true><<<dim3(2, cdiv(N, 128)), 256>>>(bufA, W1, b1, bufB, N, 32, 256);

    // --- L2: t = A*h1 (F=256) -> bufA ; h2 = relu(t@W2+b2) -> bufB [N,1024] ---
    k_csragg<64><<<cdiv(N, 4), 256>>>(bufB, bufA, rowptr, csr, dinv, nullptr, N);
    k_asplit<<<cdiv((long long)N * 64, 256), 256>>>(bufA, Ahi, Alo, (long long)N * 64);
    k_mma<true, true><<<dim3(8, cdiv(N, 128)), 256, SMEM_DYN>>>(Ahi, Alo, W2h, W2l, b2, bufB, N, 256, 1024);

    // --- L3: t = A*h2 (F=1024) -> bufA ; h3 = relu(t@W3+b3) -> bufB [N,1024] ---
    k_csragg<256><<<N, 256>>>(bufB, bufA, rowptr, csr, dinv, nullptr, N);
    k_asplit<<<cdiv((long long)N * 256, 256), 256>>>(bufA, Ahi, Alo, (long long)N * 256);
    k_mma<true, true><<<dim3(8, cdiv(N, 128)), 256, SMEM_DYN>>>(Ahi, Alo, W3h, W3l, b3, bufB, N, 1024, 1024);

    // --- L4 (transform-first): z = h3@W4 -> bufA [N,256]; t = A*z + b4 -> bufB ---
    k_asplit<<<cdiv((long long)N * 256, 256), 256>>>(bufB, Ahi, Alo, (long long)N * 256);
    k_mma<false, false><<<dim3(2, cdiv(N, 128)), 256, SMEM_DYN>>>(Ahi, Alo, W4h, W4l, nullptr, bufA, N, 1024, 256);
    k_csragg<64><<<cdiv(N, 4), 256>>>(bufA, bufB, rowptr, csr, dinv, b4, N);

    // --- L5: z6 = relu(bufB)@W5 ; out = A*z6 + b5 ---
    k_gemm_relu_256x6<<<cdiv(N, 8), 256>>>(bufB, W5, z6, N);
    k_csragg6<<<cdiv(N, 32), 256>>>(z6, out, rowptr, csr, dinv, b5, N);
}

// round 11
// speedup vs baseline: 2.7388x; 1.0379x over previous
#include <cuda_runtime.h>
#include <cuda_bf16.h>
#include <cstdint>

// ---------------------------------------------------------------------------
// GCN5: 5-layer GCN, N=100000, E=3.2M, dims 32->256->1024->1024->256->6
// R9: fused fp32->bf16 hi/lo splits into csragg / mma epilogues (no k_asplit).
// ---------------------------------------------------------------------------

__device__ float g_bufA[102400000];   // 100000 * 1024
__device__ float g_bufB[102400000];   // 100000 * 1024
__device__ float g_z6[600064];
__device__ float g_dinv[100000];
__device__ int   g_is64;

__device__ int g_cnt[100000];
__device__ int g_rowptr[100001];
__device__ int g_next[100000];
__device__ int g_csr[3300000];
__device__ int g_bsum[512];

__device__ __align__(128) __nv_bfloat16 g_Ahi[102400000];
__device__ __align__(128) __nv_bfloat16 g_Alo[102400000];
__device__ __align__(128) __nv_bfloat16 g_Chi[102400000];
__device__ __align__(128) __nv_bfloat16 g_Clo[102400000];
__device__ __align__(128) __nv_bfloat16 g_W2h[262144], g_W2l[262144];
__device__ __align__(128) __nv_bfloat16 g_W3h[1048576], g_W3l[1048576];
__device__ __align__(128) __nv_bfloat16 g_W4h[262144], g_W4l[262144];

// ---------------------------------------------------------------------------
// edge dtype detection
// ---------------------------------------------------------------------------
__global__ void k_detect(const unsigned* __restrict__ w, int npairs) {
    __shared__ int any;
    if (threadIdx.x == 0) any = 0;
    __syncthreads();
    for (int i = threadIdx.x; i < npairs; i += blockDim.x)
        if (w[2 * i + 1] != 0u) any = 1;
    __syncthreads();
    if (threadIdx.x == 0) g_is64 = (any == 0) ? 1 : 0;
}

__device__ __forceinline__ void edge_get(const void* ei, int E, int e, int& s, int& d) {
    if (g_is64) {
        const long long* p = (const long long*)ei;
        s = (int)p[e]; d = (int)p[E + e];
    } else {
        const int* p = (const int*)ei;
        s = p[e]; d = p[E + e];
    }
}

// ---------------------------------------------------------------------------
// CSR build
// ---------------------------------------------------------------------------
__global__ void k_zeroi(int* __restrict__ p, int n) {
    int i = blockIdx.x * blockDim.x + threadIdx.x;
    if (i < n) p[i] = 0;
}
__global__ void k_count(const void* __restrict__ ei, int* __restrict__ cnt, int E) {
    int e = blockIdx.x * blockDim.x + threadIdx.x;
    if (e >= E) return;
    int s, d; edge_get(ei, E, e, s, d);
    atomicAdd(&cnt[d], 1);
}
__global__ void k_scan1(const int* __restrict__ cnt, int* __restrict__ pre,
                        int* __restrict__ bsum, int n) {
    __shared__ int sm[256];
    int i = blockIdx.x * 256 + threadIdx.x;
    int v = (i < n) ? cnt[i] : 0;
    sm[threadIdx.x] = v;
    __syncthreads();
    for (int off = 1; off < 256; off <<= 1) {
        int t = (threadIdx.x >= off) ? sm[threadIdx.x - off] : 0;
        __syncthreads();
        sm[threadIdx.x] += t;
        __syncthreads();
    }
    if (i < n) pre[i] = sm[threadIdx.x] - v;
    if (threadIdx.x == 255) bsum[blockIdx.x] = sm[255];
}
__global__ void k_scan2(int* __restrict__ bsum, int nb) {
    __shared__ int sm[512];
    int v = (threadIdx.x < nb) ? bsum[threadIdx.x] : 0;
    sm[threadIdx.x] = v;
    __syncthreads();
    for (int off = 1; off < 512; off <<= 1) {
        int t = (threadIdx.x >= off) ? sm[threadIdx.x - off] : 0;
        __syncthreads();
        sm[threadIdx.x] += t;
        __syncthreads();
    }
    if (threadIdx.x < nb) bsum[threadIdx.x] = sm[threadIdx.x] - v;
}
__global__ void k_scan3(int* __restrict__ pre, const int* __restrict__ bsum, int n, int E) {
    int i = blockIdx.x * 256 + threadIdx.x;
    if (i < n) pre[i] += bsum[blockIdx.x];
    if (i == 0) pre[n] = E;
}
__global__ void k_dinv2(const int* __restrict__ cnt, float* __restrict__ dinv, int n) {
    int i = blockIdx.x * blockDim.x + threadIdx.x;
    if (i < n) dinv[i] = rsqrtf((float)cnt[i] + 1.0f);
}
__global__ void k_copy(int* __restrict__ dst, const int* __restrict__ src, int n) {
    int i = blockIdx.x * blockDim.x + threadIdx.x;
    if (i < n) dst[i] = src[i];
}
__global__ void k_fill(const void* __restrict__ ei, int* __restrict__ next,
                       int* __restrict__ csr, int E) {
    int e = blockIdx.x * blockDim.x + threadIdx.x;
    if (e >= E) return;
    int s, d; edge_get(ei, E, e, s, d);
    int pos = atomicAdd(&next[d], 1);
    csr[pos] = s;
}

// ---------------------------------------------------------------------------
// split helper
// ---------------------------------------------------------------------------
__device__ __forceinline__ void split2(float a, float b,
                                       __nv_bfloat162& hi, __nv_bfloat162& lo) {
    __nv_bfloat16 h0 = __float2bfloat16_rn(a), h1 = __float2bfloat16_rn(b);
    hi = __nv_bfloat162(h0, h1);
    lo = __nv_bfloat162(__float2bfloat16_rn(a - __bfloat162float(h0)),
                        __float2bfloat16_rn(b - __bfloat162float(h1)));
}

// ---------------------------------------------------------------------------
// CSR pull aggregation: r = dinv[d]*(sum_in dinv[s]*h[s] + dinv[d]*h[d]) + bias
// OUT_BF16: write bf16 hi/lo pair (fused split) instead of fp32.
// ---------------------------------------------------------------------------
template<int F4, bool OUT_BF16>
__global__ __launch_bounds__(256)
void k_csragg(const float* __restrict__ h, float* __restrict__ out,
              __nv_bfloat16* __restrict__ ohi, __nv_bfloat16* __restrict__ olo,
              const int* __restrict__ rowptr, const int* __restrict__ csr,
              const float* __restrict__ dinv, const float* __restrict__ bias, int n) {
    constexpr int NPB = 256 / F4;
    int node = blockIdx.x * NPB + threadIdx.x / F4;
    int lane = threadIdx.x % F4;
    if (node >= n) return;
    int beg = __ldg(&rowptr[node]);
    int end = __ldg(&rowptr[node + 1]);
    const float4* h4 = reinterpret_cast<const float4*>(h);
    float4 acc = make_float4(0.f, 0.f, 0.f, 0.f);
#pragma unroll 4
    for (int j = beg; j < end; j++) {
        int s = __ldg(&csr[j]);
        float w = __ldg(&dinv[s]);
        float4 v = __ldg(&h4[(long long)s * F4 + lane]);
        acc.x += w * v.x; acc.y += w * v.y; acc.z += w * v.z; acc.w += w * v.w;
    }
    float dn = dinv[node];
    float4 hv = __ldg(&h4[(long long)node * F4 + lane]);
    acc.x = (acc.x + dn * hv.x) * dn;
    acc.y = (acc.y + dn * hv.y) * dn;
    acc.z = (acc.z + dn * hv.z) * dn;
    acc.w = (acc.w + dn * hv.w) * dn;
    if (bias) {
        float4 b = reinterpret_cast<const float4*>(bias)[lane];
        acc.x += b.x; acc.y += b.y; acc.z += b.z; acc.w += b.w;
    }
    if (OUT_BF16) {
        __nv_bfloat162 h01, l01, h23, l23;
        split2(acc.x, acc.y, h01, l01);
        split2(acc.z, acc.w, h23, l23);
        long long base = (long long)node * F4 * 2 + lane * 2;   // in bf16x2 units
        reinterpret_cast<__nv_bfloat162*>(ohi)[base]     = h01;
        reinterpret_cast<__nv_bfloat162*>(ohi)[base + 1] = h23;
        reinterpret_cast<__nv_bfloat162*>(olo)[base]     = l01;
        reinterpret_cast<__nv_bfloat162*>(olo)[base + 1] = l23;
    } else {
        reinterpret_cast<float4*>(out)[(long long)node * F4 + lane] = acc;
    }
}

// F=6 variant (8 threads per node)
__global__ __launch_bounds__(256)
void k_csragg6(const float* __restrict__ z, float* __restrict__ out,
               const int* __restrict__ rowptr, const int* __restrict__ csr,
               const float* __restrict__ dinv, const float* __restrict__ bias, int n) {
    int node = blockIdx.x * 32 + threadIdx.x / 8;
    int lane = threadIdx.x % 8;
    if (node >= n) return;
    int beg = __ldg(&rowptr[node]);
    int end = __ldg(&rowptr[node + 1]);
    float acc = 0.f;
    for (int j = beg; j < end; j++) {
        int s = __ldg(&csr[j]);
        if (lane < 6) acc += __ldg(&dinv[s]) * __ldg(&z[(long long)s * 6 + lane]);
    }
    float dn = dinv[node];
    if (lane < 6)
        out[(long long)node * 6 + lane] =
            (acc + dn * __ldg(&z[(long long)node * 6 + lane])) * dn + bias[lane];
}

// W[K,N] -> Wt_hi/lo[N,K]
__global__ void k_wsplit(const float* __restrict__ W, __nv_bfloat16* __restrict__ th,
                         __nv_bfloat16* __restrict__ tl, int K, int N) {
    int i = blockIdx.x * blockDim.x + threadIdx.x;
    if (i >= K * N) return;
    int k = i / N, n = i - k * N;
    float w = W[i];
    __nv_bfloat16 h = __float2bfloat16_rn(w);
    __nv_bfloat16 l = __float2bfloat16_rn(w - __bfloat162float(h));
    th[(long long)n * K + k] = h;
    tl[(long long)n * K + k] = l;
}

// ---------------------------------------------------------------------------
// mma.sync bf16 GEMM (3-term fp32 split), 128x128x32 tile, cp.async 2-stage.
// OUT_BF16: fused bias+relu+split epilogue -> Chi/Clo.
// ---------------------------------------------------------------------------
__device__ __forceinline__ uint32_t smem_u32(const void* p) {
    uint32_t a;
    asm("{ .reg .u64 t; cvta.to.shared.u64 t, %1; cvt.u32.u64 %0, t; }" : "=r"(a) : "l"(p));
    return a;
}
__device__ __forceinline__ void cp16(uint32_t dst, const void* src, bool v) {
    asm volatile("cp.async.cg.shared.global [%0], [%1], 16, %2;"
                 :: "r"(dst), "l"(src), "r"(v ? 16 : 0) : "memory");
}
__device__ __forceinline__ uint32_t lds32(const __nv_bfloat16* p) {
    return *reinterpret_cast<const uint32_t*>(p);
}
__device__ __forceinline__ void mma16816(float* c, const uint32_t* a, const uint32_t* b) {
    asm volatile("mma.sync.aligned.m16n8k16.row.col.f32.bf16.bf16.f32 "
                 "{%0,%1,%2,%3}, {%4,%5,%6,%7}, {%8,%9}, {%0,%1,%2,%3};"
                 : "+f"(c[0]), "+f"(c[1]), "+f"(c[2]), "+f"(c[3])
                 : "r"(a[0]), "r"(a[1]), "r"(a[2]), "r"(a[3]), "r"(b[0]), "r"(b[1]));
}

#define STG_STRIDE 20480
#define ROW_ST 40

template<bool RELU, bool HAS_BIAS, bool OUT_BF16>
__global__ __launch_bounds__(256)
void k_mma(const __nv_bfloat16* __restrict__ Ah, const __nv_bfloat16* __restrict__ Al,
           const __nv_bfloat16* __restrict__ Bh, const __nv_bfloat16* __restrict__ Bl,
           const float* __restrict__ bias, float* __restrict__ C,
           __nv_bfloat16* __restrict__ Chi, __nv_bfloat16* __restrict__ Clo,
           int M, int K, int N) {
    extern __shared__ __align__(16) __nv_bfloat16 sm[];
    const int tid = threadIdx.x;
    const int wid = tid >> 5, lane = tid & 31;
    const int wm = wid & 3, wn = wid >> 2;
    const int gid = lane >> 2, tq = lane & 3;
    const int m0 = blockIdx.y * 128, n0 = blockIdx.x * 128;

    float acc[2][8][4];
#pragma unroll
    for (int a = 0; a < 2; a++)
#pragma unroll
        for (int b = 0; b < 8; b++)
#pragma unroll
            for (int c = 0; c < 4; c++) acc[a][b][c] = 0.f;

    const int nK = K >> 5;

    auto issue = [&](int it, int s) {
        int k0 = it << 5;
#pragma unroll
        for (int i = 0; i < 2; i++) {
            int idx = tid + i * 256;
            int row = idx >> 2, g = idx & 3;
            uint32_t so = (uint32_t)s * STG_STRIDE + row * ROW_ST + g * 8;
            bool av = (m0 + row) < M;
            size_t gA = (size_t)(m0 + row) * K + k0 + g * 8;
            cp16(smem_u32(sm + so),          Ah + (av ? gA : 0), av);
            cp16(smem_u32(sm + so + 5120),   Al + (av ? gA : 0), av);
            size_t gB = (size_t)(n0 + row) * K + k0 + g * 8;
            cp16(smem_u32(sm + so + 10240),  Bh + gB, true);
            cp16(smem_u32(sm + so + 15360),  Bl + gB, true);
        }
        asm volatile("cp.async.commit_group;" ::: "memory");
    };

    issue(0, 0);
    for (int it = 0; it < nK; ++it) {
        if (it + 1 < nK) {
            issue(it + 1, (it + 1) & 1);
            asm volatile("cp.async.wait_group 1;" ::: "memory");
        } else {
            asm volatile("cp.async.wait_group 0;" ::: "memory");
        }
        __syncthreads();

        const __nv_bfloat16* sbase = sm + (uint32_t)(it & 1) * STG_STRIDE;
#pragma unroll
        for (int kk = 0; kk < 32; kk += 16) {
            uint32_t ah[2][4], al[2][4];
#pragma unroll
            for (int mt = 0; mt < 2; mt++) {
                const __nv_bfloat16* p = sbase + (wm * 32 + mt * 16 + gid) * ROW_ST + kk + tq * 2;
                ah[mt][0] = lds32(p);
                ah[mt][1] = lds32(p + 8 * ROW_ST);
                ah[mt][2] = lds32(p + 8);
                ah[mt][3] = lds32(p + 8 * ROW_ST + 8);
                al[mt][0] = lds32(p + 5120);
                al[mt][1] = lds32(p + 5120 + 8 * ROW_ST);
                al[mt][2] = lds32(p + 5120 + 8);
                al[mt][3] = lds32(p + 5120 + 8 * ROW_ST + 8);
            }
#pragma unroll
            for (int nt = 0; nt < 8; nt++) {
                const __nv_bfloat16* q = sbase + 10240 + (wn * 64 + nt * 8 + gid) * ROW_ST + kk + tq * 2;
                uint32_t bh[2] = { lds32(q), lds32(q + 8) };
                uint32_t bl[2] = { lds32(q + 5120), lds32(q + 5120 + 8) };
#pragma unroll
                for (int mt = 0; mt < 2; mt++) {
                    mma16816(acc[mt][nt], ah[mt], bh);
                    mma16816(acc[mt][nt], ah[mt], bl);
                    mma16816(acc[mt][nt], al[mt], bh);
                }
            }
        }
        __syncthreads();
    }

#pragma unroll
    for (int mt = 0; mt < 2; mt++) {
#pragma unroll
        for (int half = 0; half < 2; half++) {
            int row = m0 + wm * 32 + mt * 16 + gid + half * 8;
            if (row >= M) continue;
#pragma unroll
            for (int nt = 0; nt < 8; nt++) {
                int col = nt * 8 + tq * 2;
                float v0 = acc[mt][nt][half * 2 + 0];
                float v1 = acc[mt][nt][half * 2 + 1];
                if (HAS_BIAS) {
                    const float* bp = bias + n0 + wn * 64 + col;
                    v0 += bp[0]; v1 += bp[1];
                }
                if (RELU) { v0 = fmaxf(v0, 0.f); v1 = fmaxf(v1, 0.f); }
                if (OUT_BF16) {
                    __nv_bfloat162 h, l;
                    split2(v0, v1, h, l);
                    size_t o = ((size_t)row * N + n0 + wn * 64 + col) >> 1;  // bf16x2 units
                    reinterpret_cast<__nv_bfloat162*>(Chi)[o] = h;
                    reinterpret_cast<__nv_bfloat162*>(Clo)[o] = l;
                } else {
                    float* cp = C + (size_t)row * N + n0 + wn * 64;
                    *reinterpret_cast<float2*>(cp + col) = make_float2(v0, v1);
                }
            }
        }
    }
}

// ---------------------------------------------------------------------------
// FFMA SGEMM (L1, K=32)
// ---------------------------------------------------------------------------
template<bool RELU_OUT, bool HAS_BIAS>
__global__ __launch_bounds__(256)
void k_sgemm(const float* __restrict__ A, const float* __restrict__ B,
             const float* __restrict__ bias, float* __restrict__ C,
             int M, int K, int N) {
    constexpr int BM = 128, BN = 128, BK = 8, TM = 8, TN = 8;
    __shared__ float As[BK][BM];
    __shared__ float Bs[BK][BN];
    int tid = threadIdx.x;
    int tr = tid / 16, tc = tid % 16;
    float acc[TM][TN];
#pragma unroll
    for (int i = 0; i < TM; i++)
#pragma unroll
        for (int j = 0; j < TN; j++) acc[i][j] = 0.f;
    int aRow = tid >> 1, aCol = (tid & 1) << 2;
    int bRow = tid >> 5, bCol = (tid & 31) << 2;
    long long aGRow = (long long)blockIdx.y * BM + aRow;
    const bool aValid = aGRow < M;
    const float* Aptr = A + aGRow * (long long)K + aCol;
    const float* Bptr = B + (long long)bRow * N + (long long)blockIdx.x * BN + bCol;
    for (int k0 = 0; k0 < K; k0 += BK) {
        float4 av = make_float4(0.f, 0.f, 0.f, 0.f);
        if (aValid) av = *reinterpret_cast<const float4*>(Aptr + k0);
        As[aCol + 0][aRow] = av.x; As[aCol + 1][aRow] = av.y;
        As[aCol + 2][aRow] = av.z; As[aCol + 3][aRow] = av.w;
        float4 bv = *reinterpret_cast<const float4*>(Bptr + (long long)k0 * N);
        *reinterpret_cast<float4*>(&Bs[bRow][bCol]) = bv;
        __syncthreads();
#pragma unroll
        for (int k = 0; k < BK; k++) {
            float rm[TM], rn[TN];
#pragma unroll
            for (int i = 0; i < TM; i++) rm[i] = As[k][tr * TM + i];
#pragma unroll
            for (int j = 0; j < TN; j++) rn[j] = Bs[k][tc * TN + j];
#pragma unroll
            for (int i = 0; i < TM; i++)
#pragma unroll
                for (int j = 0; j < TN; j++) acc[i][j] += rm[i] * rn[j];
        }
        __syncthreads();
    }
#pragma unroll
    for (int i = 0; i < TM; i++) {
        long long row = (long long)blockIdx.y * BM + tr * TM + i;
        if (row >= M) continue;
#pragma unroll
        for (int j = 0; j < TN; j += 4) {
            int col = blockIdx.x * BN + tc * TN + j;
            float4 v = make_float4(acc[i][j], acc[i][j + 1], acc[i][j + 2], acc[i][j + 3]);
            if (HAS_BIAS) {
                float4 bb = *reinterpret_cast<const float4*>(bias + col);
                v.x += bb.x; v.y += bb.y; v.z += bb.z; v.w += bb.w;
            }
            if (RELU_OUT) {
                v.x = fmaxf(v.x, 0.f); v.y = fmaxf(v.y, 0.f);
                v.z = fmaxf(v.z, 0.f); v.w = fmaxf(v.w, 0.f);
            }
            *reinterpret_cast<float4*>(C + row * (long long)N + col) = v;
        }
    }
}

// ---------------------------------------------------------------------------
// L5: z = relu(A[M,256]) @ W[256,6]
// ---------------------------------------------------------------------------
__global__ void k_gemm_relu_256x6(const float* __restrict__ A, const float* __restrict__ W,
                                  float* __restrict__ C, int M) {
    __shared__ float Ws[256 * 6];
    for (int i = threadIdx.x; i < 256 * 6; i += blockDim.x) Ws[i] = W[i];
    __syncthreads();
    int warp = threadIdx.x >> 5, lane = threadIdx.x & 31;
    long long row = (long long)blockIdx.x * 8 + warp;
    if (row >= M) return;
    float a0 = 0.f, a1 = 0.f, a2 = 0.f, a3 = 0.f, a4 = 0.f, a5 = 0.f;
    const float* a = A + row * 256;
#pragma unroll
    for (int k0 = 0; k0 < 256; k0 += 32) {
        float av = fmaxf(a[k0 + lane], 0.f);
        const float* w = &Ws[(k0 + lane) * 6];
        a0 += av * w[0]; a1 += av * w[1]; a2 += av * w[2];
        a3 += av * w[3]; a4 += av * w[4]; a5 += av * w[5];
    }
#pragma unroll
    for (int off = 16; off > 0; off >>= 1) {
        a0 += __shfl_down_sync(0xffffffffu, a0, off);
        a1 += __shfl_down_sync(0xffffffffu, a1, off);
        a2 += __shfl_down_sync(0xffffffffu, a2, off);
        a3 += __shfl_down_sync(0xffffffffu, a3, off);
        a4 += __shfl_down_sync(0xffffffffu, a4, off);
        a5 += __shfl_down_sync(0xffffffffu, a5, off);
    }
    if (lane == 0) {
        float* c = C + row * 6;
        c[0] = a0; c[1] = a1; c[2] = a2; c[3] = a3; c[4] = a4; c[5] = a5;
    }
}

// ---------------------------------------------------------------------------

static inline unsigned cdiv(long long a, long long b) { return (unsigned)((a + b - 1) / b); }

extern "C" void kernel_launch(void* const* d_in, const int* in_sizes, int n_in,
                              void* d_out, int out_size) {
    const float* x  = (const float*)d_in[0];
    const void*  ei = d_in[1];
    const float* W1 = (const float*)d_in[2];  const float* b1 = (const float*)d_in[3];
    const float* W2 = (const float*)d_in[4];  const float* b2 = (const float*)d_in[5];
    const float* W3 = (const float*)d_in[6];  const float* b3 = (const float*)d_in[7];
    const float* W4 = (const float*)d_in[8];  const float* b4 = (const float*)d_in[9];
    const float* W5 = (const float*)d_in[10]; const float* b5 = (const float*)d_in[11];

    int N = in_sizes[0] / 32;
    int E = in_sizes[1] / 2;
    float* out = (float*)d_out;

    float *bufA, *bufB, *z6, *dinv;
    int *cnt, *rowptr, *nxt, *csr, *bsum;
    __nv_bfloat16 *Ahi, *Alo, *Chi, *Clo, *W2h, *W2l, *W3h, *W3l, *W4h, *W4l;
    cudaGetSymbolAddress((void**)&bufA, g_bufA);
    cudaGetSymbolAddress((void**)&bufB, g_bufB);
    cudaGetSymbolAddress((void**)&z6,   g_z6);
    cudaGetSymbolAddress((void**)&dinv, g_dinv);
    cudaGetSymbolAddress((void**)&cnt,    g_cnt);
    cudaGetSymbolAddress((void**)&rowptr, g_rowptr);
    cudaGetSymbolAddress((void**)&nxt,    g_next);
    cudaGetSymbolAddress((void**)&csr,    g_csr);
    cudaGetSymbolAddress((void**)&bsum,   g_bsum);
    cudaGetSymbolAddress((void**)&Ahi,  g_Ahi);
    cudaGetSymbolAddress((void**)&Alo,  g_Alo);
    cudaGetSymbolAddress((void**)&Chi,  g_Chi);
    cudaGetSymbolAddress((void**)&Clo,  g_Clo);
    cudaGetSymbolAddress((void**)&W2h,  g_W2h); cudaGetSymbolAddress((void**)&W2l, g_W2l);
    cudaGetSymbolAddress((void**)&W3h,  g_W3h); cudaGetSymbolAddress((void**)&W3l, g_W3l);
    cudaGetSymbolAddress((void**)&W4h,  g_W4h); cudaGetSymbolAddress((void**)&W4l, g_W4l);

    const int SMEM_DYN = 2 * STG_STRIDE * 2;   // 81920 B
    cudaFuncSetAttribute((const void*)k_mma<true, true, false>,  cudaFuncAttributeMaxDynamicSharedMemorySize, SMEM_DYN);
    cudaFuncSetAttribute((const void*)k_mma<true, true, true>,   cudaFuncAttributeMaxDynamicSharedMemorySize, SMEM_DYN);
    cudaFuncSetAttribute((const void*)k_mma<false, false, false>, cudaFuncAttributeMaxDynamicSharedMemorySize, SMEM_DYN);

    // --- edge dtype + CSR build ---
    int npairs = (2 * E < 8192) ? E : 4096;
    k_detect<<<1, 256>>>((const unsigned*)ei, npairs);
    k_zeroi<<<cdiv(N, 256), 256>>>(cnt, N);
    k_count<<<cdiv(E, 256), 256>>>(ei, cnt, E);
    int nb = cdiv(N, 256);
    k_scan1<<<nb, 256>>>(cnt, rowptr, bsum, N);
    k_scan2<<<1, 512>>>(bsum, nb);
    k_scan3<<<nb, 256>>>(rowptr, bsum, N, E);
    k_dinv2<<<cdiv(N, 256), 256>>>(cnt, dinv, N);
    k_copy<<<cdiv(N, 256), 256>>>(nxt, rowptr, N);
    k_fill<<<cdiv(E, 256), 256>>>(ei, nxt, csr, E);

    // --- weight transposes + splits ---
    k_wsplit<<<cdiv(256 * 1024, 256), 256>>>(W2, W2h, W2l, 256, 1024);
    k_wsplit<<<cdiv(1024 * 1024, 256), 256>>>(W3, W3h, W3l, 1024, 1024);
    k_wsplit<<<cdiv(1024 * 256, 256), 256>>>(W4, W4h, W4l, 1024, 256);

    // --- L1: t = A*x (F=32) -> bufA ; h1 = relu(t@W1+b1) -> bufB [N,256] ---
    k_csragg<8, false><<<cdiv(N, 32), 256>>>(x, bufA, nullptr, nullptr, rowptr, csr, dinv, nullptr, N);
    k_sgemm<true, true><<<dim3(2, cdiv(N, 128)), 256>>>(bufA, W1, b1, bufB, N, 32, 256);

    // --- L2: t = A*h1 (F=256, split-fused) -> Ahi/Alo ; h2 = relu(t@W2+b2) -> bufB [N,1024] ---
    k_csragg<64, true><<<cdiv(N, 4), 256>>>(bufB, nullptr, Ahi, Alo, rowptr, csr, dinv, nullptr, N);
    k_mma<true, true, false><<<dim3(8, cdiv(N, 128)), 256, SMEM_DYN>>>(Ahi, Alo, W2h, W2l, b2, bufB, nullptr, nullptr, N, 256, 1024);

    // --- L3: t = A*h2 (F=1024, split-fused) -> Ahi/Alo ; h3 = relu(t@W3+b3) -> Chi/Clo (bf16) ---
    k_csragg<256, true><<<N, 256>>>(bufB, nullptr, Ahi, Alo, rowptr, csr, dinv, nullptr, N);
    k_mma<true, true, true><<<dim3(8, cdiv(N, 128)), 256, SMEM_DYN>>>(Ahi, Alo, W3h, W3l, b3, nullptr, Chi, Clo, N, 1024, 1024);

    // --- L4 (transform-first): z = h3@W4 -> bufA [N,256]; t = A*z + b4 -> bufB ---
    k_mma<false, false, false><<<dim3(2, cdiv(N, 128)), 256, SMEM_DYN>>>(Chi, Clo, W4h, W4l, nullptr, bufA, nullptr, nullptr, N, 1024, 256);
    k_csragg<64, false><<<cdiv(N, 4), 256>>>(bufA, bufB, nullptr, nullptr, rowptr, csr, dinv, b4, N);

    // --- L5: z6 = relu(bufB)@W5 ; out = A*z6 + b5 ---
    k_gemm_relu_256x6<<<cdiv(N, 8), 256>>>(bufB, W5, z6, N);
    k_csragg6<<<cdiv(N, 32), 256>>>(z6, out, rowptr, csr, dinv, b5, N);
}

// round 13
// speedup vs baseline: 3.1342x; 1.1444x over previous
#include <cuda_runtime.h>
#include <cuda_bf16.h>
#include <cstdint>

// ---------------------------------------------------------------------------
// GCN5: 5-layer GCN, N=100000, E=3.2M, dims 32->256->1024->1024->256->6
// R13: re-land L3 feature-chunked aggregation, hardened:
//      256-thread blocks (4 nodes x 64 lanes), streaming (write-through)
//      stores so chunk writes don't evict the L2-resident gather table.
// ---------------------------------------------------------------------------

__device__ float g_bufA[102400000];   // 100000 * 1024
__device__ float g_bufB[102400000];   // 100000 * 1024
__device__ float g_z6[600064];
__device__ float g_dinv[100000];
__device__ int   g_is64;

__device__ int g_cnt[100000];
__device__ int g_rowptr[100001];
__device__ int g_next[100000];
__device__ int g_csr[3300000];
__device__ int g_bsum[512];

__device__ __align__(128) __nv_bfloat16 g_Ahi[102400000];
__device__ __align__(128) __nv_bfloat16 g_Alo[102400000];
__device__ __align__(128) __nv_bfloat16 g_Chi[102400000];
__device__ __align__(128) __nv_bfloat16 g_Clo[102400000];
__device__ __align__(128) __nv_bfloat16 g_W2h[262144], g_W2l[262144];
__device__ __align__(128) __nv_bfloat16 g_W3h[1048576], g_W3l[1048576];
__device__ __align__(128) __nv_bfloat16 g_W4h[262144], g_W4l[262144];

// ---------------------------------------------------------------------------
// edge dtype detection
// ---------------------------------------------------------------------------
__global__ void k_detect(const unsigned* __restrict__ w, int npairs) {
    __shared__ int any;
    if (threadIdx.x == 0) any = 0;
    __syncthreads();
    for (int i = threadIdx.x; i < npairs; i += blockDim.x)
        if (w[2 * i + 1] != 0u) any = 1;
    __syncthreads();
    if (threadIdx.x == 0) g_is64 = (any == 0) ? 1 : 0;
}

__device__ __forceinline__ void edge_get(const void* ei, int E, int e, int& s, int& d) {
    if (g_is64) {
        const long long* p = (const long long*)ei;
        s = (int)p[e]; d = (int)p[E + e];
    } else {
        const int* p = (const int*)ei;
        s = p[e]; d = p[E + e];
    }
}

// ---------------------------------------------------------------------------
// CSR build
// ---------------------------------------------------------------------------
__global__ void k_zeroi(int* __restrict__ p, int n) {
    int i = blockIdx.x * blockDim.x + threadIdx.x;
    if (i < n) p[i] = 0;
}
__global__ void k_count(const void* __restrict__ ei, int* __restrict__ cnt, int E) {
    int e = blockIdx.x * blockDim.x + threadIdx.x;
    if (e >= E) return;
    int s, d; edge_get(ei, E, e, s, d);
    atomicAdd(&cnt[d], 1);
}
__global__ void k_scan1(const int* __restrict__ cnt, int* __restrict__ pre,
                        int* __restrict__ bsum, int n) {
    __shared__ int sm[256];
    int i = blockIdx.x * 256 + threadIdx.x;
    int v = (i < n) ? cnt[i] : 0;
    sm[threadIdx.x] = v;
    __syncthreads();
    for (int off = 1; off < 256; off <<= 1) {
        int t = (threadIdx.x >= off) ? sm[threadIdx.x - off] : 0;
        __syncthreads();
        sm[threadIdx.x] += t;
        __syncthreads();
    }
    if (i < n) pre[i] = sm[threadIdx.x] - v;
    if (threadIdx.x == 255) bsum[blockIdx.x] = sm[255];
}
__global__ void k_scan2(int* __restrict__ bsum, int nb) {
    __shared__ int sm[512];
    int v = (threadIdx.x < nb) ? bsum[threadIdx.x] : 0;
    sm[threadIdx.x] = v;
    __syncthreads();
    for (int off = 1; off < 512; off <<= 1) {
        int t = (threadIdx.x >= off) ? sm[threadIdx.x - off] : 0;
        __syncthreads();
        sm[threadIdx.x] += t;
        __syncthreads();
    }
    if (threadIdx.x < nb) bsum[threadIdx.x] = sm[threadIdx.x] - v;
}
__global__ void k_scan3(int* __restrict__ pre, const int* __restrict__ bsum, int n, int E) {
    int i = blockIdx.x * 256 + threadIdx.x;
    if (i < n) pre[i] += bsum[blockIdx.x];
    if (i == 0) pre[n] = E;
}
__global__ void k_dinv2(const int* __restrict__ cnt, float* __restrict__ dinv, int n) {
    int i = blockIdx.x * blockDim.x + threadIdx.x;
    if (i < n) dinv[i] = rsqrtf((float)cnt[i] + 1.0f);
}
__global__ void k_copy(int* __restrict__ dst, const int* __restrict__ src, int n) {
    int i = blockIdx.x * blockDim.x + threadIdx.x;
    if (i < n) dst[i] = src[i];
}
__global__ void k_fill(const void* __restrict__ ei, int* __restrict__ next,
                       int* __restrict__ csr, int E) {
    int e = blockIdx.x * blockDim.x + threadIdx.x;
    if (e >= E) return;
    int s, d; edge_get(ei, E, e, s, d);
    int pos = atomicAdd(&next[d], 1);
    csr[pos] = s;
}

// ---------------------------------------------------------------------------
// split helper
// ---------------------------------------------------------------------------
__device__ __forceinline__ void split2(float a, float b,
                                       __nv_bfloat162& hi, __nv_bfloat162& lo) {
    __nv_bfloat16 h0 = __float2bfloat16_rn(a), h1 = __float2bfloat16_rn(b);
    hi = __nv_bfloat162(h0, h1);
    lo = __nv_bfloat162(__float2bfloat16_rn(a - __bfloat162float(h0)),
                        __float2bfloat16_rn(b - __bfloat162float(h1)));
}
__device__ __forceinline__ uint32_t b2u(__nv_bfloat162 v) {
    uint32_t u;
    __builtin_memcpy(&u, &v, 4);
    return u;
}

// ---------------------------------------------------------------------------
// CSR pull aggregation: r = dinv[d]*(sum_in dinv[s]*h[s] + dinv[d]*h[d]) + bias
// OUT_BF16: write bf16 hi/lo pair (fused split) instead of fp32.
// ---------------------------------------------------------------------------
template<int F4, bool OUT_BF16>
__global__ __launch_bounds__(256)
void k_csragg(const float* __restrict__ h, float* __restrict__ out,
              __nv_bfloat16* __restrict__ ohi, __nv_bfloat16* __restrict__ olo,
              const int* __restrict__ rowptr, const int* __restrict__ csr,
              const float* __restrict__ dinv, const float* __restrict__ bias, int n) {
    constexpr int NPB = 256 / F4;
    int node = blockIdx.x * NPB + threadIdx.x / F4;
    int lane = threadIdx.x % F4;
    if (node >= n) return;
    int beg = __ldg(&rowptr[node]);
    int end = __ldg(&rowptr[node + 1]);
    const float4* h4 = reinterpret_cast<const float4*>(h);
    float4 acc = make_float4(0.f, 0.f, 0.f, 0.f);
#pragma unroll 4
    for (int j = beg; j < end; j++) {
        int s = __ldg(&csr[j]);
        float w = __ldg(&dinv[s]);
        float4 v = __ldg(&h4[(long long)s * F4 + lane]);
        acc.x += w * v.x; acc.y += w * v.y; acc.z += w * v.z; acc.w += w * v.w;
    }
    float dn = dinv[node];
    float4 hv = __ldg(&h4[(long long)node * F4 + lane]);
    acc.x = (acc.x + dn * hv.x) * dn;
    acc.y = (acc.y + dn * hv.y) * dn;
    acc.z = (acc.z + dn * hv.z) * dn;
    acc.w = (acc.w + dn * hv.w) * dn;
    if (bias) {
        float4 b = reinterpret_cast<const float4*>(bias)[lane];
        acc.x += b.x; acc.y += b.y; acc.z += b.z; acc.w += b.w;
    }
    if (OUT_BF16) {
        __nv_bfloat162 h01, l01, h23, l23;
        split2(acc.x, acc.y, h01, l01);
        split2(acc.z, acc.w, h23, l23);
        long long base = (long long)node * F4 * 2 + lane * 2;
        reinterpret_cast<__nv_bfloat162*>(ohi)[base]     = h01;
        reinterpret_cast<__nv_bfloat162*>(ohi)[base + 1] = h23;
        reinterpret_cast<__nv_bfloat162*>(olo)[base]     = l01;
        reinterpret_cast<__nv_bfloat162*>(olo)[base + 1] = l23;
    } else {
        reinterpret_cast<float4*>(out)[(long long)node * F4 + lane] = acc;
    }
}

// Feature-chunked variant for F=1024 rows. blockIdx.y = chunk (slow axis).
// 256 threads = 4 nodes x 64 lanes (same proven shape as k_csragg).
// Streaming stores (st.global.wt) keep the gather sub-table resident in L2.
template<int F4TOT, int F4CHUNK>
__global__ __launch_bounds__(256)
void k_csragg_chunk(const float* __restrict__ h,
                    __nv_bfloat16* __restrict__ ohi, __nv_bfloat16* __restrict__ olo,
                    const int* __restrict__ rowptr, const int* __restrict__ csr,
                    const float* __restrict__ dinv, int n) {
    int node = blockIdx.x * 4 + threadIdx.x / F4CHUNK;
    int lane = threadIdx.x % F4CHUNK;
    if (node >= n) return;
    int coff = blockIdx.y * F4CHUNK + lane;
    int beg = __ldg(&rowptr[node]);
    int end = __ldg(&rowptr[node + 1]);
    const float4* h4 = reinterpret_cast<const float4*>(h);
    float4 acc = make_float4(0.f, 0.f, 0.f, 0.f);
#pragma unroll 4
    for (int j = beg; j < end; j++) {
        int s = __ldg(&csr[j]);
        float w = __ldg(&dinv[s]);
        float4 v = __ldg(&h4[(long long)s * F4TOT + coff]);
        acc.x += w * v.x; acc.y += w * v.y; acc.z += w * v.z; acc.w += w * v.w;
    }
    float dn = dinv[node];
    float4 hv = __ldg(&h4[(long long)node * F4TOT + coff]);
    acc.x = (acc.x + dn * hv.x) * dn;
    acc.y = (acc.y + dn * hv.y) * dn;
    acc.z = (acc.z + dn * hv.z) * dn;
    acc.w = (acc.w + dn * hv.w) * dn;
    __nv_bfloat162 h01, l01, h23, l23;
    split2(acc.x, acc.y, h01, l01);
    split2(acc.z, acc.w, h23, l23);
    long long base = (long long)node * F4TOT * 2 + coff * 2;   // uint32 units
    uint32_t* ph = reinterpret_cast<uint32_t*>(ohi) + base;
    uint32_t* pl = reinterpret_cast<uint32_t*>(olo) + base;
    asm volatile("st.global.wt.v2.b32 [%0], {%1, %2};"
                 :: "l"(ph), "r"(b2u(h01)), "r"(b2u(h23)) : "memory");
    asm volatile("st.global.wt.v2.b32 [%0], {%1, %2};"
                 :: "l"(pl), "r"(b2u(l01)), "r"(b2u(l23)) : "memory");
}

// F=6 variant (8 threads per node)
__global__ __launch_bounds__(256)
void k_csragg6(const float* __restrict__ z, float* __restrict__ out,
               const int* __restrict__ rowptr, const int* __restrict__ csr,
               const float* __restrict__ dinv, const float* __restrict__ bias, int n) {
    int node = blockIdx.x * 32 + threadIdx.x / 8;
    int lane = threadIdx.x % 8;
    if (node >= n) return;
    int beg = __ldg(&rowptr[node]);
    int end = __ldg(&rowptr[node + 1]);
    float acc = 0.f;
    for (int j = beg; j < end; j++) {
        int s = __ldg(&csr[j]);
        if (lane < 6) acc += __ldg(&dinv[s]) * __ldg(&z[(long long)s * 6 + lane]);
    }
    float dn = dinv[node];
    if (lane < 6)
        out[(long long)node * 6 + lane] =
            (acc + dn * __ldg(&z[(long long)node * 6 + lane])) * dn + bias[lane];
}

// W[K,N] -> Wt_hi/lo[N,K]
__global__ void k_wsplit(const float* __restrict__ W, __nv_bfloat16* __restrict__ th,
                         __nv_bfloat16* __restrict__ tl, int K, int N) {
    int i = blockIdx.x * blockDim.x + threadIdx.x;
    if (i >= K * N) return;
    int k = i / N, n = i - k * N;
    float w = W[i];
    __nv_bfloat16 h = __float2bfloat16_rn(w);
    __nv_bfloat16 l = __float2bfloat16_rn(w - __bfloat162float(h));
    th[(long long)n * K + k] = h;
    tl[(long long)n * K + k] = l;
}

// ---------------------------------------------------------------------------
// mma.sync bf16 GEMM (3-term fp32 split), 128x128x32 tile, cp.async 2-stage.
// ---------------------------------------------------------------------------
__device__ __forceinline__ uint32_t smem_u32(const void* p) {
    uint32_t a;
    asm("{ .reg .u64 t; cvta.to.shared.u64 t, %1; cvt.u32.u64 %0, t; }" : "=r"(a) : "l"(p));
    return a;
}
__device__ __forceinline__ void cp16(uint32_t dst, const void* src, bool v) {
    asm volatile("cp.async.cg.shared.global [%0], [%1], 16, %2;"
                 :: "r"(dst), "l"(src), "r"(v ? 16 : 0) : "memory");
}
__device__ __forceinline__ uint32_t lds32(const __nv_bfloat16* p) {
    return *reinterpret_cast<const uint32_t*>(p);
}
__device__ __forceinline__ void mma16816(float* c, const uint32_t* a, const uint32_t* b) {
    asm volatile("mma.sync.aligned.m16n8k16.row.col.f32.bf16.bf16.f32 "
                 "{%0,%1,%2,%3}, {%4,%5,%6,%7}, {%8,%9}, {%0,%1,%2,%3};"
                 : "+f"(c[0]), "+f"(c[1]), "+f"(c[2]), "+f"(c[3])
                 : "r"(a[0]), "r"(a[1]), "r"(a[2]), "r"(a[3]), "r"(b[0]), "r"(b[1]));
}

#define STG_STRIDE 20480
#define ROW_ST 40

template<bool RELU, bool HAS_BIAS, bool OUT_BF16>
__global__ __launch_bounds__(256)
void k_mma(const __nv_bfloat16* __restrict__ Ah, const __nv_bfloat16* __restrict__ Al,
           const __nv_bfloat16* __restrict__ Bh, const __nv_bfloat16* __restrict__ Bl,
           const float* __restrict__ bias, float* __restrict__ C,
           __nv_bfloat16* __restrict__ Chi, __nv_bfloat16* __restrict__ Clo,
           int M, int K, int N) {
    extern __shared__ __align__(16) __nv_bfloat16 sm[];
    const int tid = threadIdx.x;
    const int wid = tid >> 5, lane = tid & 31;
    const int wm = wid & 3, wn = wid >> 2;
    const int gid = lane >> 2, tq = lane & 3;
    const int m0 = blockIdx.y * 128, n0 = blockIdx.x * 128;

    float acc[2][8][4];
#pragma unroll
    for (int a = 0; a < 2; a++)
#pragma unroll
        for (int b = 0; b < 8; b++)
#pragma unroll
            for (int c = 0; c < 4; c++) acc[a][b][c] = 0.f;

    const int nK = K >> 5;

    auto issue = [&](int it, int s) {
        int k0 = it << 5;
#pragma unroll
        for (int i = 0; i < 2; i++) {
            int idx = tid + i * 256;
            int row = idx >> 2, g = idx & 3;
            uint32_t so = (uint32_t)s * STG_STRIDE + row * ROW_ST + g * 8;
            bool av = (m0 + row) < M;
            size_t gA = (size_t)(m0 + row) * K + k0 + g * 8;
            cp16(smem_u32(sm + so),          Ah + (av ? gA : 0), av);
            cp16(smem_u32(sm + so + 5120),   Al + (av ? gA : 0), av);
            size_t gB = (size_t)(n0 + row) * K + k0 + g * 8;
            cp16(smem_u32(sm + so + 10240),  Bh + gB, true);
            cp16(smem_u32(sm + so + 15360),  Bl + gB, true);
        }
        asm volatile("cp.async.commit_group;" ::: "memory");
    };

    issue(0, 0);
    for (int it = 0; it < nK; ++it) {
        if (it + 1 < nK) {
            issue(it + 1, (it + 1) & 1);
            asm volatile("cp.async.wait_group 1;" ::: "memory");
        } else {
            asm volatile("cp.async.wait_group 0;" ::: "memory");
        }
        __syncthreads();

        const __nv_bfloat16* sbase = sm + (uint32_t)(it & 1) * STG_STRIDE;
#pragma unroll
        for (int kk = 0; kk < 32; kk += 16) {
            uint32_t ah[2][4], al[2][4];
#pragma unroll
            for (int mt = 0; mt < 2; mt++) {
                const __nv_bfloat16* p = sbase + (wm * 32 + mt * 16 + gid) * ROW_ST + kk + tq * 2;
                ah[mt][0] = lds32(p);
                ah[mt][1] = lds32(p + 8 * ROW_ST);
                ah[mt][2] = lds32(p + 8);
                ah[mt][3] = lds32(p + 8 * ROW_ST + 8);
                al[mt][0] = lds32(p + 5120);
                al[mt][1] = lds32(p + 5120 + 8 * ROW_ST);
                al[mt][2] = lds32(p + 5120 + 8);
                al[mt][3] = lds32(p + 5120 + 8 * ROW_ST + 8);
            }
#pragma unroll
            for (int nt = 0; nt < 8; nt++) {
                const __nv_bfloat16* q = sbase + 10240 + (wn * 64 + nt * 8 + gid) * ROW_ST + kk + tq * 2;
                uint32_t bh[2] = { lds32(q), lds32(q + 8) };
                uint32_t bl[2] = { lds32(q + 5120), lds32(q + 5120 + 8) };
#pragma unroll
                for (int mt = 0; mt < 2; mt++) {
                    mma16816(acc[mt][nt], ah[mt], bh);
                    mma16816(acc[mt][nt], ah[mt], bl);
                    mma16816(acc[mt][nt], al[mt], bh);
                }
            }
        }
        __syncthreads();
    }

#pragma unroll
    for (int mt = 0; mt < 2; mt++) {
#pragma unroll
        for (int half = 0; half < 2; half++) {
            int row = m0 + wm * 32 + mt * 16 + gid + half * 8;
            if (row >= M) continue;
#pragma unroll
            for (int nt = 0; nt < 8; nt++) {
                int col = nt * 8 + tq * 2;
                float v0 = acc[mt][nt][half * 2 + 0];
                float v1 = acc[mt][nt][half * 2 + 1];
                if (HAS_BIAS) {
                    const float* bp = bias + n0 + wn * 64 + col;
                    v0 += bp[0]; v1 += bp[1];
                }
                if (RELU) { v0 = fmaxf(v0, 0.f); v1 = fmaxf(v1, 0.f); }
                if (OUT_BF16) {
                    __nv_bfloat162 h, l;
                    split2(v0, v1, h, l);
                    size_t o = ((size_t)row * N + n0 + wn * 64 + col) >> 1;
                    reinterpret_cast<__nv_bfloat162*>(Chi)[o] = h;
                    reinterpret_cast<__nv_bfloat162*>(Clo)[o] = l;
                } else {
                    float* cp = C + (size_t)row * N + n0 + wn * 64;
                    *reinterpret_cast<float2*>(cp + col) = make_float2(v0, v1);
                }
            }
        }
    }
}

// ---------------------------------------------------------------------------
// FFMA SGEMM (L1, K=32)
// ---------------------------------------------------------------------------
template<bool RELU_OUT, bool HAS_BIAS>
__global__ __launch_bounds__(256)
void k_sgemm(const float* __restrict__ A, const float* __restrict__ B,
             const float* __restrict__ bias, float* __restrict__ C,
             int M, int K, int N) {
    constexpr int BM = 128, BN = 128, BK = 8, TM = 8, TN = 8;
    __shared__ float As[BK][BM];
    __shared__ float Bs[BK][BN];
    int tid = threadIdx.x;
    int tr = tid / 16, tc = tid % 16;
    float acc[TM][TN];
#pragma unroll
    for (int i = 0; i < TM; i++)
#pragma unroll
        for (int j = 0; j < TN; j++) acc[i][j] = 0.f;
    int aRow = tid >> 1, aCol = (tid & 1) << 2;
    int bRow = tid >> 5, bCol = (tid & 31) << 2;
    long long aGRow = (long long)blockIdx.y * BM + aRow;
    const bool aValid = aGRow < M;
    const float* Aptr = A + aGRow * (long long)K + aCol;
    const float* Bptr = B + (long long)bRow * N + (long long)blockIdx.x * BN + bCol;
    for (int k0 = 0; k0 < K; k0 += BK) {
        float4 av = make_float4(0.f, 0.f, 0.f, 0.f);
        if (aValid) av = *reinterpret_cast<const float4*>(Aptr + k0);
        As[aCol + 0][aRow] = av.x; As[aCol + 1][aRow] = av.y;
        As[aCol + 2][aRow] = av.z; As[aCol + 3][aRow] = av.w;
        float4 bv = *reinterpret_cast<const float4*>(Bptr + (long long)k0 * N);
        *reinterpret_cast<float4*>(&Bs[bRow][bCol]) = bv;
        __syncthreads();
#pragma unroll
        for (int k = 0; k < BK; k++) {
            float rm[TM], rn[TN];
#pragma unroll
            for (int i = 0; i < TM; i++) rm[i] = As[k][tr * TM + i];
#pragma unroll
            for (int j = 0; j < TN; j++) rn[j] = Bs[k][tc * TN + j];
#pragma unroll
            for (int i = 0; i < TM; i++)
#pragma unroll
                for (int j = 0; j < TN; j++) acc[i][j] += rm[i] * rn[j];
        }
        __syncthreads();
    }
#pragma unroll
    for (int i = 0; i < TM; i++) {
        long long row = (long long)blockIdx.y * BM + tr * TM + i;
        if (row >= M) continue;
#pragma unroll
        for (int j = 0; j < TN; j += 4) {
            int col = blockIdx.x * BN + tc * TN + j;
            float4 v = make_float4(acc[i][j], acc[i][j + 1], acc[i][j + 2], acc[i][j + 3]);
            if (HAS_BIAS) {
                float4 bb = *reinterpret_cast<const float4*>(bias + col);
                v.x += bb.x; v.y += bb.y; v.z += bb.z; v.w += bb.w;
            }
            if (RELU_OUT) {
                v.x = fmaxf(v.x, 0.f); v.y = fmaxf(v.y, 0.f);
                v.z = fmaxf(v.z, 0.f); v.w = fmaxf(v.w, 0.f);
            }
            *reinterpret_cast<float4*>(C + row * (long long)N + col) = v;
        }
    }
}

// ---------------------------------------------------------------------------
// L5: z = relu(A[M,256]) @ W[256,6]
// ---------------------------------------------------------------------------
__global__ void k_gemm_relu_256x6(const float* __restrict__ A, const float* __restrict__ W,
                                  float* __restrict__ C, int M) {
    __shared__ float Ws[256 * 6];
    for (int i = threadIdx.x; i < 256 * 6; i += blockDim.x) Ws[i] = W[i];
    __syncthreads();
    int warp = threadIdx.x >> 5, lane = threadIdx.x & 31;
    long long row = (long long)blockIdx.x * 8 + warp;
    if (row >= M) return;
    float a0 = 0.f, a1 = 0.f, a2 = 0.f, a3 = 0.f, a4 = 0.f, a5 = 0.f;
    const float* a = A + row * 256;
#pragma unroll
    for (int k0 = 0; k0 < 256; k0 += 32) {
        float av = fmaxf(a[k0 + lane], 0.f);
        const float* w = &Ws[(k0 + lane) * 6];
        a0 += av * w[0]; a1 += av * w[1]; a2 += av * w[2];
        a3 += av * w[3]; a4 += av * w[4]; a5 += av * w[5];
    }
#pragma unroll
    for (int off = 16; off > 0; off >>= 1) {
        a0 += __shfl_down_sync(0xffffffffu, a0, off);
        a1 += __shfl_down_sync(0xffffffffu, a1, off);
        a2 += __shfl_down_sync(0xffffffffu, a2, off);
        a3 += __shfl_down_sync(0xffffffffu, a3, off);
        a4 += __shfl_down_sync(0xffffffffu, a4, off);
        a5 += __shfl_down_sync(0xffffffffu, a5, off);
    }
    if (lane == 0) {
        float* c = C + row * 6;
        c[0] = a0; c[1] = a1; c[2] = a2; c[3] = a3; c[4] = a4; c[5] = a5;
    }
}

// ---------------------------------------------------------------------------

static inline unsigned cdiv(long long a, long long b) { return (unsigned)((a + b - 1) / b); }

extern "C" void kernel_launch(void* const* d_in, const int* in_sizes, int n_in,
                              void* d_out, int out_size) {
    const float* x  = (const float*)d_in[0];
    const void*  ei = d_in[1];
    const float* W1 = (const float*)d_in[2];  const float* b1 = (const float*)d_in[3];
    const float* W2 = (const float*)d_in[4];  const float* b2 = (const float*)d_in[5];
    const float* W3 = (const float*)d_in[6];  const float* b3 = (const float*)d_in[7];
    const float* W4 = (const float*)d_in[8];  const float* b4 = (const float*)d_in[9];
    const float* W5 = (const float*)d_in[10]; const float* b5 = (const float*)d_in[11];

    int N = in_sizes[0] / 32;
    int E = in_sizes[1] / 2;
    float* out = (float*)d_out;

    float *bufA, *bufB, *z6, *dinv;
    int *cnt, *rowptr, *nxt, *csr, *bsum;
    __nv_bfloat16 *Ahi, *Alo, *Chi, *Clo, *W2h, *W2l, *W3h, *W3l, *W4h, *W4l;
    cudaGetSymbolAddress((void**)&bufA, g_bufA);
    cudaGetSymbolAddress((void**)&bufB, g_bufB);
    cudaGetSymbolAddress((void**)&z6,   g_z6);
    cudaGetSymbolAddress((void**)&dinv, g_dinv);
    cudaGetSymbolAddress((void**)&cnt,    g_cnt);
    cudaGetSymbolAddress((void**)&rowptr, g_rowptr);
    cudaGetSymbolAddress((void**)&nxt,    g_next);
    cudaGetSymbolAddress((void**)&csr,    g_csr);
    cudaGetSymbolAddress((void**)&bsum,   g_bsum);
    cudaGetSymbolAddress((void**)&Ahi,  g_Ahi);
    cudaGetSymbolAddress((void**)&Alo,  g_Alo);
    cudaGetSymbolAddress((void**)&Chi,  g_Chi);
    cudaGetSymbolAddress((void**)&Clo,  g_Clo);
    cudaGetSymbolAddress((void**)&W2h,  g_W2h); cudaGetSymbolAddress((void**)&W2l, g_W2l);
    cudaGetSymbolAddress((void**)&W3h,  g_W3h); cudaGetSymbolAddress((void**)&W3l, g_W3l);
    cudaGetSymbolAddress((void**)&W4h,  g_W4h); cudaGetSymbolAddress((void**)&W4l, g_W4l);

    const int SMEM_DYN = 2 * STG_STRIDE * 2;   // 81920 B
    cudaFuncSetAttribute((const void*)k_mma<true, true, false>,  cudaFuncAttributeMaxDynamicSharedMemorySize, SMEM_DYN);
    cudaFuncSetAttribute((const void*)k_mma<true, true, true>,   cudaFuncAttributeMaxDynamicSharedMemorySize, SMEM_DYN);
    cudaFuncSetAttribute((const void*)k_mma<false, false, false>, cudaFuncAttributeMaxDynamicSharedMemorySize, SMEM_DYN);

    // --- edge dtype + CSR build ---
    int npairs = (2 * E < 8192) ? E : 4096;
    k_detect<<<1, 256>>>((const unsigned*)ei, npairs);
    k_zeroi<<<cdiv(N, 256), 256>>>(cnt, N);
    k_count<<<cdiv(E, 256), 256>>>(ei, cnt, E);
    int nb = cdiv(N, 256);
    k_scan1<<<nb, 256>>>(cnt, rowptr, bsum, N);
    k_scan2<<<1, 512>>>(bsum, nb);
    k_scan3<<<nb, 256>>>(rowptr, bsum, N, E);
    k_dinv2<<<cdiv(N, 256), 256>>>(cnt, dinv, N);
    k_copy<<<cdiv(N, 256), 256>>>(nxt, rowptr, N);
    k_fill<<<cdiv(E, 256), 256>>>(ei, nxt, csr, E);

    // --- weight transposes + splits ---
    k_wsplit<<<cdiv(256 * 1024, 256), 256>>>(W2, W2h, W2l, 256, 1024);
    k_wsplit<<<cdiv(1024 * 1024, 256), 256>>>(W3, W3h, W3l, 1024, 1024);
    k_wsplit<<<cdiv(1024 * 256, 256), 256>>>(W4, W4h, W4l, 1024, 256);

    // --- L1: t = A*x (F=32) -> bufA ; h1 = relu(t@W1+b1) -> bufB [N,256] ---
    k_csragg<8, false><<<cdiv(N, 32), 256>>>(x, bufA, nullptr, nullptr, rowptr, csr, dinv, nullptr, N);
    k_sgemm<true, true><<<dim3(2, cdiv(N, 128)), 256>>>(bufA, W1, b1, bufB, N, 32, 256);

    // --- L2: t = A*h1 (F=256, split-fused) -> Ahi/Alo ; h2 = relu(t@W2+b2) -> bufB [N,1024] ---
    k_csragg<64, true><<<cdiv(N, 4), 256>>>(bufB, nullptr, Ahi, Alo, rowptr, csr, dinv, nullptr, N);
    k_mma<true, true, false><<<dim3(8, cdiv(N, 128)), 256, SMEM_DYN>>>(Ahi, Alo, W2h, W2l, b2, bufB, nullptr, nullptr, N, 256, 1024);

    // --- L3: t = A*h2 (F=1024, chunked for L2 residency, streaming stores) -> Ahi/Alo ;
    //     h3 = relu(t@W3+b3) -> Chi/Clo (bf16) ---
    k_csragg_chunk<256, 64><<<dim3(cdiv(N, 4), 4), 256>>>(bufB, Ahi, Alo, rowptr, csr, dinv, N);
    k_mma<true, true, true><<<dim3(8, cdiv(N, 128)), 256, SMEM_DYN>>>(Ahi, Alo, W3h, W3l, b3, nullptr, Chi, Clo, N, 1024, 1024);

    // --- L4 (transform-first): z = h3@W4 -> bufA [N,256]; t = A*z + b4 -> bufB ---
    k_mma<false, false, false><<<dim3(2, cdiv(N, 128)), 256, SMEM_DYN>>>(Chi, Clo, W4h, W4l, nullptr, bufA, nullptr, nullptr, N, 1024, 256);
    k_csragg<64, false><<<cdiv(N, 4), 256>>>(bufA, bufB, nullptr, nullptr, rowptr, csr, dinv, b4, N);

    // --- L5: z6 = relu(bufB)@W5 ; out = A*z6 + b5 ---
    k_gemm_relu_256x6<<<cdiv(N, 8), 256>>>(bufB, W5, z6, N);
    k_csragg6<<<cdiv(N, 32), 256>>>(z6, out, rowptr, csr, dinv, b5, N);
}

// round 15
// speedup vs baseline: 3.1467x; 1.0040x over previous
#include <cuda_runtime.h>
#include <cuda_bf16.h>
#include <cstdint>

// ---------------------------------------------------------------------------
// GCN5: 5-layer GCN, N=100000, E=3.2M, dims 32->256->1024->1024->256->6
// R14: streaming (write-through) stores on L2-agg and L4-agg outputs so the
//      100MB gather tables stay L2-resident (extends R13's proven win).
// ---------------------------------------------------------------------------

__device__ float g_bufA[102400000];   // 100000 * 1024
__device__ float g_bufB[102400000];   // 100000 * 1024
__device__ float g_z6[600064];
__device__ float g_dinv[100000];
__device__ int   g_is64;

__device__ int g_cnt[100000];
__device__ int g_rowptr[100001];
__device__ int g_next[100000];
__device__ int g_csr[3300000];
__device__ int g_bsum[512];

__device__ __align__(128) __nv_bfloat16 g_Ahi[102400000];
__device__ __align__(128) __nv_bfloat16 g_Alo[102400000];
__device__ __align__(128) __nv_bfloat16 g_Chi[102400000];
__device__ __align__(128) __nv_bfloat16 g_Clo[102400000];
__device__ __align__(128) __nv_bfloat16 g_W2h[262144], g_W2l[262144];
__device__ __align__(128) __nv_bfloat16 g_W3h[1048576], g_W3l[1048576];
__device__ __align__(128) __nv_bfloat16 g_W4h[262144], g_W4l[262144];

// ---------------------------------------------------------------------------
// edge dtype detection
// ---------------------------------------------------------------------------
__global__ void k_detect(const unsigned* __restrict__ w, int npairs) {
    __shared__ int any;
    if (threadIdx.x == 0) any = 0;
    __syncthreads();
    for (int i = threadIdx.x; i < npairs; i += blockDim.x)
        if (w[2 * i + 1] != 0u) any = 1;
    __syncthreads();
    if (threadIdx.x == 0) g_is64 = (any == 0) ? 1 : 0;
}

__device__ __forceinline__ void edge_get(const void* ei, int E, int e, int& s, int& d) {
    if (g_is64) {
        const long long* p = (const long long*)ei;
        s = (int)p[e]; d = (int)p[E + e];
    } else {
        const int* p = (const int*)ei;
        s = p[e]; d = p[E + e];
    }
}

// ---------------------------------------------------------------------------
// CSR build
// ---------------------------------------------------------------------------
__global__ void k_zeroi(int* __restrict__ p, int n) {
    int i = blockIdx.x * blockDim.x + threadIdx.x;
    if (i < n) p[i] = 0;
}
__global__ void k_count(const void* __restrict__ ei, int* __restrict__ cnt, int E) {
    int e = blockIdx.x * blockDim.x + threadIdx.x;
    if (e >= E) return;
    int s, d; edge_get(ei, E, e, s, d);
    atomicAdd(&cnt[d], 1);
}
__global__ void k_scan1(const int* __restrict__ cnt, int* __restrict__ pre,
                        int* __restrict__ bsum, int n) {
    __shared__ int sm[256];
    int i = blockIdx.x * 256 + threadIdx.x;
    int v = (i < n) ? cnt[i] : 0;
    sm[threadIdx.x] = v;
    __syncthreads();
    for (int off = 1; off < 256; off <<= 1) {
        int t = (threadIdx.x >= off) ? sm[threadIdx.x - off] : 0;
        __syncthreads();
        sm[threadIdx.x] += t;
        __syncthreads();
    }
    if (i < n) pre[i] = sm[threadIdx.x] - v;
    if (threadIdx.x == 255) bsum[blockIdx.x] = sm[255];
}
__global__ void k_scan2(int* __restrict__ bsum, int nb) {
    __shared__ int sm[512];
    int v = (threadIdx.x < nb) ? bsum[threadIdx.x] : 0;
    sm[threadIdx.x] = v;
    __syncthreads();
    for (int off = 1; off < 512; off <<= 1) {
        int t = (threadIdx.x >= off) ? sm[threadIdx.x - off] : 0;
        __syncthreads();
        sm[threadIdx.x] += t;
        __syncthreads();
    }
    if (threadIdx.x < nb) bsum[threadIdx.x] = sm[threadIdx.x] - v;
}
__global__ void k_scan3(int* __restrict__ pre, const int* __restrict__ bsum, int n, int E) {
    int i = blockIdx.x * 256 + threadIdx.x;
    if (i < n) pre[i] += bsum[blockIdx.x];
    if (i == 0) pre[n] = E;
}
__global__ void k_dinv2(const int* __restrict__ cnt, float* __restrict__ dinv, int n) {
    int i = blockIdx.x * blockDim.x + threadIdx.x;
    if (i < n) dinv[i] = rsqrtf((float)cnt[i] + 1.0f);
}
__global__ void k_copy(int* __restrict__ dst, const int* __restrict__ src, int n) {
    int i = blockIdx.x * blockDim.x + threadIdx.x;
    if (i < n) dst[i] = src[i];
}
__global__ void k_fill(const void* __restrict__ ei, int* __restrict__ next,
                       int* __restrict__ csr, int E) {
    int e = blockIdx.x * blockDim.x + threadIdx.x;
    if (e >= E) return;
    int s, d; edge_get(ei, E, e, s, d);
    int pos = atomicAdd(&next[d], 1);
    csr[pos] = s;
}

// ---------------------------------------------------------------------------
// split helper + streaming store helpers
// ---------------------------------------------------------------------------
__device__ __forceinline__ void split2(float a, float b,
                                       __nv_bfloat162& hi, __nv_bfloat162& lo) {
    __nv_bfloat16 h0 = __float2bfloat16_rn(a), h1 = __float2bfloat16_rn(b);
    hi = __nv_bfloat162(h0, h1);
    lo = __nv_bfloat162(__float2bfloat16_rn(a - __bfloat162float(h0)),
                        __float2bfloat16_rn(b - __bfloat162float(h1)));
}
__device__ __forceinline__ uint32_t b2u(__nv_bfloat162 v) {
    uint32_t u;
    __builtin_memcpy(&u, &v, 4);
    return u;
}
__device__ __forceinline__ void stwt2(uint32_t* p, uint32_t a, uint32_t b) {
    asm volatile("st.global.wt.v2.b32 [%0], {%1, %2};" :: "l"(p), "r"(a), "r"(b) : "memory");
}
__device__ __forceinline__ void stwt4f(float* p, float4 v) {
    asm volatile("st.global.wt.v4.f32 [%0], {%1, %2, %3, %4};"
                 :: "l"(p), "f"(v.x), "f"(v.y), "f"(v.z), "f"(v.w) : "memory");
}

// ---------------------------------------------------------------------------
// CSR pull aggregation: r = dinv[d]*(sum_in dinv[s]*h[s] + dinv[d]*h[d]) + bias
// OUT_BF16: fused bf16 hi/lo split output. STREAM: write-through stores so
// the output never evicts the L2-resident gather table.
// ---------------------------------------------------------------------------
template<int F4, bool OUT_BF16, bool STREAM>
__global__ __launch_bounds__(256)
void k_csragg(const float* __restrict__ h, float* __restrict__ out,
              __nv_bfloat16* __restrict__ ohi, __nv_bfloat16* __restrict__ olo,
              const int* __restrict__ rowptr, const int* __restrict__ csr,
              const float* __restrict__ dinv, const float* __restrict__ bias, int n) {
    constexpr int NPB = 256 / F4;
    int node = blockIdx.x * NPB + threadIdx.x / F4;
    int lane = threadIdx.x % F4;
    if (node >= n) return;
    int beg = __ldg(&rowptr[node]);
    int end = __ldg(&rowptr[node + 1]);
    const float4* h4 = reinterpret_cast<const float4*>(h);
    float4 acc = make_float4(0.f, 0.f, 0.f, 0.f);
#pragma unroll 4
    for (int j = beg; j < end; j++) {
        int s = __ldg(&csr[j]);
        float w = __ldg(&dinv[s]);
        float4 v = __ldg(&h4[(long long)s * F4 + lane]);
        acc.x += w * v.x; acc.y += w * v.y; acc.z += w * v.z; acc.w += w * v.w;
    }
    float dn = dinv[node];
    float4 hv = __ldg(&h4[(long long)node * F4 + lane]);
    acc.x = (acc.x + dn * hv.x) * dn;
    acc.y = (acc.y + dn * hv.y) * dn;
    acc.z = (acc.z + dn * hv.z) * dn;
    acc.w = (acc.w + dn * hv.w) * dn;
    if (bias) {
        float4 b = reinterpret_cast<const float4*>(bias)[lane];
        acc.x += b.x; acc.y += b.y; acc.z += b.z; acc.w += b.w;
    }
    if (OUT_BF16) {
        __nv_bfloat162 h01, l01, h23, l23;
        split2(acc.x, acc.y, h01, l01);
        split2(acc.z, acc.w, h23, l23);
        long long base = (long long)node * F4 * 2 + lane * 2;   // uint32 units
        if (STREAM) {
            stwt2(reinterpret_cast<uint32_t*>(ohi) + base, b2u(h01), b2u(h23));
            stwt2(reinterpret_cast<uint32_t*>(olo) + base, b2u(l01), b2u(l23));
        } else {
            reinterpret_cast<__nv_bfloat162*>(ohi)[base]     = h01;
            reinterpret_cast<__nv_bfloat162*>(ohi)[base + 1] = h23;
            reinterpret_cast<__nv_bfloat162*>(olo)[base]     = l01;
            reinterpret_cast<__nv_bfloat162*>(olo)[base + 1] = l23;
        }
    } else {
        if (STREAM)
            stwt4f(out + ((long long)node * F4 + lane) * 4, acc);
        else
            reinterpret_cast<float4*>(out)[(long long)node * F4 + lane] = acc;
    }
}

// Feature-chunked variant for F=1024 rows (L3). blockIdx.y = chunk (slow axis).
template<int F4TOT, int F4CHUNK>
__global__ __launch_bounds__(256)
void k_csragg_chunk(const float* __restrict__ h,
                    __nv_bfloat16* __restrict__ ohi, __nv_bfloat16* __restrict__ olo,
                    const int* __restrict__ rowptr, const int* __restrict__ csr,
                    const float* __restrict__ dinv, int n) {
    int node = blockIdx.x * 4 + threadIdx.x / F4CHUNK;
    int lane = threadIdx.x % F4CHUNK;
    if (node >= n) return;
    int coff = blockIdx.y * F4CHUNK + lane;
    int beg = __ldg(&rowptr[node]);
    int end = __ldg(&rowptr[node + 1]);
    const float4* h4 = reinterpret_cast<const float4*>(h);
    float4 acc = make_float4(0.f, 0.f, 0.f, 0.f);
#pragma unroll 4
    for (int j = beg; j < end; j++) {
        int s = __ldg(&csr[j]);
        float w = __ldg(&dinv[s]);
        float4 v = __ldg(&h4[(long long)s * F4TOT + coff]);
        acc.x += w * v.x; acc.y += w * v.y; acc.z += w * v.z; acc.w += w * v.w;
    }
    float dn = dinv[node];
    float4 hv = __ldg(&h4[(long long)node * F4TOT + coff]);
    acc.x = (acc.x + dn * hv.x) * dn;
    acc.y = (acc.y + dn * hv.y) * dn;
    acc.z = (acc.z + dn * hv.z) * dn;
    acc.w = (acc.w + dn * hv.w) * dn;
    __nv_bfloat162 h01, l01, h23, l23;
    split2(acc.x, acc.y, h01, l01);
    split2(acc.z, acc.w, h23, l23);
    long long base = (long long)node * F4TOT * 2 + coff * 2;   // uint32 units
    stwt2(reinterpret_cast<uint32_t*>(ohi) + base, b2u(h01), b2u(h23));
    stwt2(reinterpret_cast<uint32_t*>(olo) + base, b2u(l01), b2u(l23));
}

// F=6 variant (8 threads per node)
__global__ __launch_bounds__(256)
void k_csragg6(const float* __restrict__ z, float* __restrict__ out,
               const int* __restrict__ rowptr, const int* __restrict__ csr,
               const float* __restrict__ dinv, const float* __restrict__ bias, int n) {
    int node = blockIdx.x * 32 + threadIdx.x / 8;
    int lane = threadIdx.x % 8;
    if (node >= n) return;
    int beg = __ldg(&rowptr[node]);
    int end = __ldg(&rowptr[node + 1]);
    float acc = 0.f;
    for (int j = beg; j < end; j++) {
        int s = __ldg(&csr[j]);
        if (lane < 6) acc += __ldg(&dinv[s]) * __ldg(&z[(long long)s * 6 + lane]);
    }
    float dn = dinv[node];
    if (lane < 6)
        out[(long long)node * 6 + lane] =
            (acc + dn * __ldg(&z[(long long)node * 6 + lane])) * dn + bias[lane];
}

// W[K,N] -> Wt_hi/lo[N,K]
__global__ void k_wsplit(const float* __restrict__ W, __nv_bfloat16* __restrict__ th,
                         __nv_bfloat16* __restrict__ tl, int K, int N) {
    int i = blockIdx.x * blockDim.x + threadIdx.x;
    if (i >= K * N) return;
    int k = i / N, n = i - k * N;
    float w = W[i];
    __nv_bfloat16 h = __float2bfloat16_rn(w);
    __nv_bfloat16 l = __float2bfloat16_rn(w - __bfloat162float(h));
    th[(long long)n * K + k] = h;
    tl[(long long)n * K + k] = l;
}

// ---------------------------------------------------------------------------
// mma.sync bf16 GEMM (3-term fp32 split), 128x128x32 tile, cp.async 2-stage.
// ---------------------------------------------------------------------------
__device__ __forceinline__ uint32_t smem_u32(const void* p) {
    uint32_t a;
    asm("{ .reg .u64 t; cvta.to.shared.u64 t, %1; cvt.u32.u64 %0, t; }" : "=r"(a) : "l"(p));
    return a;
}
__device__ __forceinline__ void cp16(uint32_t dst, const void* src, bool v) {
    asm volatile("cp.async.cg.shared.global [%0], [%1], 16, %2;"
                 :: "r"(dst), "l"(src), "r"(v ? 16 : 0) : "memory");
}
__device__ __forceinline__ uint32_t lds32(const __nv_bfloat16* p) {
    return *reinterpret_cast<const uint32_t*>(p);
}
__device__ __forceinline__ void mma16816(float* c, const uint32_t* a, const uint32_t* b) {
    asm volatile("mma.sync.aligned.m16n8k16.row.col.f32.bf16.bf16.f32 "
                 "{%0,%1,%2,%3}, {%4,%5,%6,%7}, {%8,%9}, {%0,%1,%2,%3};"
                 : "+f"(c[0]), "+f"(c[1]), "+f"(c[2]), "+f"(c[3])
                 : "r"(a[0]), "r"(a[1]), "r"(a[2]), "r"(a[3]), "r"(b[0]), "r"(b[1]));
}

#define STG_STRIDE 20480
#define ROW_ST 40

template<bool RELU, bool HAS_BIAS, bool OUT_BF16>
__global__ __launch_bounds__(256)
void k_mma(const __nv_bfloat16* __restrict__ Ah, const __nv_bfloat16* __restrict__ Al,
           const __nv_bfloat16* __restrict__ Bh, const __nv_bfloat16* __restrict__ Bl,
           const float* __restrict__ bias, float* __restrict__ C,
           __nv_bfloat16* __restrict__ Chi, __nv_bfloat16* __restrict__ Clo,
           int M, int K, int N) {
    extern __shared__ __align__(16) __nv_bfloat16 sm[];
    const int tid = threadIdx.x;
    const int wid = tid >> 5, lane = tid & 31;
    const int wm = wid & 3, wn = wid >> 2;
    const int gid = lane >> 2, tq = lane & 3;
    const int m0 = blockIdx.y * 128, n0 = blockIdx.x * 128;

    float acc[2][8][4];
#pragma unroll
    for (int a = 0; a < 2; a++)
#pragma unroll
        for (int b = 0; b < 8; b++)
#pragma unroll
            for (int c = 0; c < 4; c++) acc[a][b][c] = 0.f;

    const int nK = K >> 5;

    auto issue = [&](int it, int s) {
        int k0 = it << 5;
#pragma unroll
        for (int i = 0; i < 2; i++) {
            int idx = tid + i * 256;
            int row = idx >> 2, g = idx & 3;
            uint32_t so = (uint32_t)s * STG_STRIDE + row * ROW_ST + g * 8;
            bool av = (m0 + row) < M;
            size_t gA = (size_t)(m0 + row) * K + k0 + g * 8;
            cp16(smem_u32(sm + so),          Ah + (av ? gA : 0), av);
            cp16(smem_u32(sm + so + 5120),   Al + (av ? gA : 0), av);
            size_t gB = (size_t)(n0 + row) * K + k0 + g * 8;
            cp16(smem_u32(sm + so + 10240),  Bh + gB, true);
            cp16(smem_u32(sm + so + 15360),  Bl + gB, true);
        }
        asm volatile("cp.async.commit_group;" ::: "memory");
    };

    issue(0, 0);
    for (int it = 0; it < nK; ++it) {
        if (it + 1 < nK) {
            issue(it + 1, (it + 1) & 1);
            asm volatile("cp.async.wait_group 1;" ::: "memory");
        } else {
            asm volatile("cp.async.wait_group 0;" ::: "memory");
        }
        __syncthreads();

        const __nv_bfloat16* sbase = sm + (uint32_t)(it & 1) * STG_STRIDE;
#pragma unroll
        for (int kk = 0; kk < 32; kk += 16) {
            uint32_t ah[2][4], al[2][4];
#pragma unroll
            for (int mt = 0; mt < 2; mt++) {
                const __nv_bfloat16* p = sbase + (wm * 32 + mt * 16 + gid) * ROW_ST + kk + tq * 2;
                ah[mt][0] = lds32(p);
                ah[mt][1] = lds32(p + 8 * ROW_ST);
                ah[mt][2] = lds32(p + 8);
                ah[mt][3] = lds32(p + 8 * ROW_ST + 8);
                al[mt][0] = lds32(p + 5120);
                al[mt][1] = lds32(p + 5120 + 8 * ROW_ST);
                al[mt][2] = lds32(p + 5120 + 8);
                al[mt][3] = lds32(p + 5120 + 8 * ROW_ST + 8);
            }
#pragma unroll
            for (int nt = 0; nt < 8; nt++) {
                const __nv_bfloat16* q = sbase + 10240 + (wn * 64 + nt * 8 + gid) * ROW_ST + kk + tq * 2;
                uint32_t bh[2] = { lds32(q), lds32(q + 8) };
                uint32_t bl[2] = { lds32(q + 5120), lds32(q + 5120 + 8) };
#pragma unroll
                for (int mt = 0; mt < 2; mt++) {
                    mma16816(acc[mt][nt], ah[mt], bh);
                    mma16816(acc[mt][nt], ah[mt], bl);
                    mma16816(acc[mt][nt], al[mt], bh);
                }
            }
        }
        __syncthreads();
    }

#pragma unroll
    for (int mt = 0; mt < 2; mt++) {
#pragma unroll
        for (int half = 0; half < 2; half++) {
            int row = m0 + wm * 32 + mt * 16 + gid + half * 8;
            if (row >= M) continue;
#pragma unroll
            for (int nt = 0; nt < 8; nt++) {
                int col = nt * 8 + tq * 2;
                float v0 = acc[mt][nt][half * 2 + 0];
                float v1 = acc[mt][nt][half * 2 + 1];
                if (HAS_BIAS) {
                    const float* bp = bias + n0 + wn * 64 + col;
                    v0 += bp[0]; v1 += bp[1];
                }
                if (RELU) { v0 = fmaxf(v0, 0.f); v1 = fmaxf(v1, 0.f); }
                if (OUT_BF16) {
                    __nv_bfloat162 h, l;
                    split2(v0, v1, h, l);
                    size_t o = ((size_t)row * N + n0 + wn * 64 + col) >> 1;
                    reinterpret_cast<__nv_bfloat162*>(Chi)[o] = h;
                    reinterpret_cast<__nv_bfloat162*>(Clo)[o] = l;
                } else {
                    float* cp = C + (size_t)row * N + n0 + wn * 64;
                    *reinterpret_cast<float2*>(cp + col) = make_float2(v0, v1);
                }
            }
        }
    }
}

// ---------------------------------------------------------------------------
// FFMA SGEMM (L1, K=32)
// ---------------------------------------------------------------------------
template<bool RELU_OUT, bool HAS_BIAS>
__global__ __launch_bounds__(256)
void k_sgemm(const float* __restrict__ A, const float* __restrict__ B,
             const float* __restrict__ bias, float* __restrict__ C,
             int M, int K, int N) {
    constexpr int BM = 128, BN = 128, BK = 8, TM = 8, TN = 8;
    __shared__ float As[BK][BM];
    __shared__ float Bs[BK][BN];
    int tid = threadIdx.x;
    int tr = tid / 16, tc = tid % 16;
    float acc[TM][TN];
#pragma unroll
    for (int i = 0; i < TM; i++)
#pragma unroll
        for (int j = 0; j < TN; j++) acc[i][j] = 0.f;
    int aRow = tid >> 1, aCol = (tid & 1) << 2;
    int bRow = tid >> 5, bCol = (tid & 31) << 2;
    long long aGRow = (long long)blockIdx.y * BM + aRow;
    const bool aValid = aGRow < M;
    const float* Aptr = A + aGRow * (long long)K + aCol;
    const float* Bptr = B + (long long)bRow * N + (long long)blockIdx.x * BN + bCol;
    for (int k0 = 0; k0 < K; k0 += BK) {
        float4 av = make_float4(0.f, 0.f, 0.f, 0.f);
        if (aValid) av = *reinterpret_cast<const float4*>(Aptr + k0);
        As[aCol + 0][aRow] = av.x; As[aCol + 1][aRow] = av.y;
        As[aCol + 2][aRow] = av.z; As[aCol + 3][aRow] = av.w;
        float4 bv = *reinterpret_cast<const float4*>(Bptr + (long long)k0 * N);
        *reinterpret_cast<float4*>(&Bs[bRow][bCol]) = bv;
        __syncthreads();
#pragma unroll
        for (int k = 0; k < BK; k++) {
            float rm[TM], rn[TN];
#pragma unroll
            for (int i = 0; i < TM; i++) rm[i] = As[k][tr * TM + i];
#pragma unroll
            for (int j = 0; j < TN; j++) rn[j] = Bs[k][tc * TN + j];
#pragma unroll
            for (int i = 0; i < TM; i++)
#pragma unroll
                for (int j = 0; j < TN; j++) acc[i][j] += rm[i] * rn[j];
        }
        __syncthreads();
    }
#pragma unroll
    for (int i = 0; i < TM; i++) {
        long long row = (long long)blockIdx.y * BM + tr * TM + i;
        if (row >= M) continue;
#pragma unroll
        for (int j = 0; j < TN; j += 4) {
            int col = blockIdx.x * BN + tc * TN + j;
            float4 v = make_float4(acc[i][j], acc[i][j + 1], acc[i][j + 2], acc[i][j + 3]);
            if (HAS_BIAS) {
                float4 bb = *reinterpret_cast<const float4*>(bias + col);
                v.x += bb.x; v.y += bb.y; v.z += bb.z; v.w += bb.w;
            }
            if (RELU_OUT) {
                v.x = fmaxf(v.x, 0.f); v.y = fmaxf(v.y, 0.f);
                v.z = fmaxf(v.z, 0.f); v.w = fmaxf(v.w, 0.f);
            }
            *reinterpret_cast<float4*>(C + row * (long long)N + col) = v;
        }
    }
}

// ---------------------------------------------------------------------------
// L5: z = relu(A[M,256]) @ W[256,6]
// ---------------------------------------------------------------------------
__global__ void k_gemm_relu_256x6(const float* __restrict__ A, const float* __restrict__ W,
                                  float* __restrict__ C, int M) {
    __shared__ float Ws[256 * 6];
    for (int i = threadIdx.x; i < 256 * 6; i += blockDim.x) Ws[i] = W[i];
    __syncthreads();
    int warp = threadIdx.x >> 5, lane = threadIdx.x & 31;
    long long row = (long long)blockIdx.x * 8 + warp;
    if (row >= M) return;
    float a0 = 0.f, a1 = 0.f, a2 = 0.f, a3 = 0.f, a4 = 0.f, a5 = 0.f;
    const float* a = A + row * 256;
#pragma unroll
    for (int k0 = 0; k0 < 256; k0 += 32) {
        float av = fmaxf(a[k0 + lane], 0.f);
        const float* w = &Ws[(k0 + lane) * 6];
        a0 += av * w[0]; a1 += av * w[1]; a2 += av * w[2];
        a3 += av * w[3]; a4 += av * w[4]; a5 += av * w[5];
    }
#pragma unroll
    for (int off = 16; off > 0; off >>= 1) {
        a0 += __shfl_down_sync(0xffffffffu, a0, off);
        a1 += __shfl_down_sync(0xffffffffu, a1, off);
        a2 += __shfl_down_sync(0xffffffffu, a2, off);
        a3 += __shfl_down_sync(0xffffffffu, a3, off);
        a4 += __shfl_down_sync(0xffffffffu, a4, off);
        a5 += __shfl_down_sync(0xffffffffu, a5, off);
    }
    if (lane == 0) {
        float* c = C + row * 6;
        c[0] = a0; c[1] = a1; c[2] = a2; c[3] = a3; c[4] = a4; c[5] = a5;
    }
}

// ---------------------------------------------------------------------------

static inline unsigned cdiv(long long a, long long b) { return (unsigned)((a + b - 1) / b); }

extern "C" void kernel_launch(void* const* d_in, const int* in_sizes, int n_in,
                              void* d_out, int out_size) {
    const float* x  = (const float*)d_in[0];
    const void*  ei = d_in[1];
    const float* W1 = (const float*)d_in[2];  const float* b1 = (const float*)d_in[3];
    const float* W2 = (const float*)d_in[4];  const float* b2 = (const float*)d_in[5];
    const float* W3 = (const float*)d_in[6];  const float* b3 = (const float*)d_in[7];
    const float* W4 = (const float*)d_in[8];  const float* b4 = (const float*)d_in[9];
    const float* W5 = (const float*)d_in[10]; const float* b5 = (const float*)d_in[11];

    int N = in_sizes[0] / 32;
    int E = in_sizes[1] / 2;
    float* out = (float*)d_out;

    float *bufA, *bufB, *z6, *dinv;
    int *cnt, *rowptr, *nxt, *csr, *bsum;
    __nv_bfloat16 *Ahi, *Alo, *Chi, *Clo, *W2h, *W2l, *W3h, *W3l, *W4h, *W4l;
    cudaGetSymbolAddress((void**)&bufA, g_bufA);
    cudaGetSymbolAddress((void**)&bufB, g_bufB);
    cudaGetSymbolAddress((void**)&z6,   g_z6);
    cudaGetSymbolAddress((void**)&dinv, g_dinv);
    cudaGetSymbolAddress((void**)&cnt,    g_cnt);
    cudaGetSymbolAddress((void**)&rowptr, g_rowptr);
    cudaGetSymbolAddress((void**)&nxt,    g_next);
    cudaGetSymbolAddress((void**)&csr,    g_csr);
    cudaGetSymbolAddress((void**)&bsum,   g_bsum);
    cudaGetSymbolAddress((void**)&Ahi,  g_Ahi);
    cudaGetSymbolAddress((void**)&Alo,  g_Alo);
    cudaGetSymbolAddress((void**)&Chi,  g_Chi);
    cudaGetSymbolAddress((void**)&Clo,  g_Clo);
    cudaGetSymbolAddress((void**)&W2h,  g_W2h); cudaGetSymbolAddress((void**)&W2l, g_W2l);
    cudaGetSymbolAddress((void**)&W3h,  g_W3h); cudaGetSymbolAddress((void**)&W3l, g_W3l);
    cudaGetSymbolAddress((void**)&W4h,  g_W4h); cudaGetSymbolAddress((void**)&W4l, g_W4l);

    const int SMEM_DYN = 2 * STG_STRIDE * 2;   // 81920 B
    cudaFuncSetAttribute((const void*)k_mma<true, true, false>,  cudaFuncAttributeMaxDynamicSharedMemorySize, SMEM_DYN);
    cudaFuncSetAttribute((const void*)k_mma<true, true, true>,   cudaFuncAttributeMaxDynamicSharedMemorySize, SMEM_DYN);
    cudaFuncSetAttribute((const void*)k_mma<false, false, false>, cudaFuncAttributeMaxDynamicSharedMemorySize, SMEM_DYN);

    // --- edge dtype + CSR build ---
    int npairs = (2 * E < 8192) ? E : 4096;
    k_detect<<<1, 256>>>((const unsigned*)ei, npairs);
    k_zeroi<<<cdiv(N, 256), 256>>>(cnt, N);
    k_count<<<cdiv(E, 256), 256>>>(ei, cnt, E);
    int nb = cdiv(N, 256);
    k_scan1<<<nb, 256>>>(cnt, rowptr, bsum, N);
    k_scan2<<<1, 512>>>(bsum, nb);
    k_scan3<<<nb, 256>>>(rowptr, bsum, N, E);
    k_dinv2<<<cdiv(N, 256), 256>>>(cnt, dinv, N);
    k_copy<<<cdiv(N, 256), 256>>>(nxt, rowptr, N);
    k_fill<<<cdiv(E, 256), 256>>>(ei, nxt, csr, E);

    // --- weight transposes + splits ---
    k_wsplit<<<cdiv(256 * 1024, 256), 256>>>(W2, W2h, W2l, 256, 1024);
    k_wsplit<<<cdiv(1024 * 1024, 256), 256>>>(W3, W3h, W3l, 1024, 1024);
    k_wsplit<<<cdiv(1024 * 256, 256), 256>>>(W4, W4h, W4l, 1024, 256);

    // --- L1: t = A*x (F=32) -> bufA ; h1 = relu(t@W1+b1) -> bufB [N,256] ---
    k_csragg<8, false, false><<<cdiv(N, 32), 256>>>(x, bufA, nullptr, nullptr, rowptr, csr, dinv, nullptr, N);
    k_sgemm<true, true><<<dim3(2, cdiv(N, 128)), 256>>>(bufA, W1, b1, bufB, N, 32, 256);

    // --- L2: t = A*h1 (F=256, split-fused, streaming out) -> Ahi/Alo ;
    //     h2 = relu(t@W2+b2) -> bufB [N,1024] ---
    k_csragg<64, true, true><<<cdiv(N, 4), 256>>>(bufB, nullptr, Ahi, Alo, rowptr, csr, dinv, nullptr, N);
    k_mma<true, true, false><<<dim3(8, cdiv(N, 128)), 256, SMEM_DYN>>>(Ahi, Alo, W2h, W2l, b2, bufB, nullptr, nullptr, N, 256, 1024);

    // --- L3: t = A*h2 (F=1024, chunked, streaming out) -> Ahi/Alo ;
    //     h3 = relu(t@W3+b3) -> Chi/Clo (bf16) ---
    k_csragg_chunk<256, 64><<<dim3(cdiv(N, 4), 4), 256>>>(bufB, Ahi, Alo, rowptr, csr, dinv, N);
    k_mma<true, true, true><<<dim3(8, cdiv(N, 128)), 256, SMEM_DYN>>>(Ahi, Alo, W3h, W3l, b3, nullptr, Chi, Clo, N, 1024, 1024);

    // --- L4 (transform-first): z = h3@W4 -> bufA [N,256]; t = A*z + b4 -> bufB (streaming) ---
    k_mma<false, false, false><<<dim3(2, cdiv(N, 128)), 256, SMEM_DYN>>>(Chi, Clo, W4h, W4l, nullptr, bufA, nullptr, nullptr, N, 1024, 256);
    k_csragg<64, false, true><<<cdiv(N, 4), 256>>>(bufA, bufB, nullptr, nullptr, rowptr, csr, dinv, b4, N);

    // --- L5: z6 = relu(bufB)@W5 ; out = A*z6 + b5 ---
    k_gemm_relu_256x6<<<cdiv(N, 8), 256>>>(bufB, W5, z6, N);
    k_csragg6<<<cdiv(N, 32), 256>>>(z6, out, rowptr, csr, dinv, b5, N);
}

// round 16
// speedup vs baseline: 3.1768x; 1.0095x over previous
#include <cuda_runtime.h>
#include <cuda_bf16.h>
#include <cstdint>

// ---------------------------------------------------------------------------
// GCN5: 5-layer GCN, N=100000, E=3.2M, dims 32->256->1024->1024->256->6
// R16: chunk L2/L4 aggregations (2 x 128-float) for guaranteed L2 residency,
//      replicating R13's L3 chunking win. Identical arithmetic per output.
// ---------------------------------------------------------------------------

__device__ float g_bufA[102400000];   // 100000 * 1024
__device__ float g_bufB[102400000];   // 100000 * 1024
__device__ float g_z6[600064];
__device__ float g_dinv[100000];
__device__ int   g_is64;

__device__ int g_cnt[100000];
__device__ int g_rowptr[100001];
__device__ int g_next[100000];
__device__ int g_csr[3300000];
__device__ int g_bsum[512];

__device__ __align__(128) __nv_bfloat16 g_Ahi[102400000];
__device__ __align__(128) __nv_bfloat16 g_Alo[102400000];
__device__ __align__(128) __nv_bfloat16 g_Chi[102400000];
__device__ __align__(128) __nv_bfloat16 g_Clo[102400000];
__device__ __align__(128) __nv_bfloat16 g_W2h[262144], g_W2l[262144];
__device__ __align__(128) __nv_bfloat16 g_W3h[1048576], g_W3l[1048576];
__device__ __align__(128) __nv_bfloat16 g_W4h[262144], g_W4l[262144];

// ---------------------------------------------------------------------------
// edge dtype detection
// ---------------------------------------------------------------------------
__global__ void k_detect(const unsigned* __restrict__ w, int npairs) {
    __shared__ int any;
    if (threadIdx.x == 0) any = 0;
    __syncthreads();
    for (int i = threadIdx.x; i < npairs; i += blockDim.x)
        if (w[2 * i + 1] != 0u) any = 1;
    __syncthreads();
    if (threadIdx.x == 0) g_is64 = (any == 0) ? 1 : 0;
}

__device__ __forceinline__ void edge_get(const void* ei, int E, int e, int& s, int& d) {
    if (g_is64) {
        const long long* p = (const long long*)ei;
        s = (int)p[e]; d = (int)p[E + e];
    } else {
        const int* p = (const int*)ei;
        s = p[e]; d = p[E + e];
    }
}

// ---------------------------------------------------------------------------
// CSR build
// ---------------------------------------------------------------------------
__global__ void k_zeroi(int* __restrict__ p, int n) {
    int i = blockIdx.x * blockDim.x + threadIdx.x;
    if (i < n) p[i] = 0;
}
__global__ void k_count(const void* __restrict__ ei, int* __restrict__ cnt, int E) {
    int e = blockIdx.x * blockDim.x + threadIdx.x;
    if (e >= E) return;
    int s, d; edge_get(ei, E, e, s, d);
    atomicAdd(&cnt[d], 1);
}
__global__ void k_scan1(const int* __restrict__ cnt, int* __restrict__ pre,
                        int* __restrict__ bsum, int n) {
    __shared__ int sm[256];
    int i = blockIdx.x * 256 + threadIdx.x;
    int v = (i < n) ? cnt[i] : 0;
    sm[threadIdx.x] = v;
    __syncthreads();
    for (int off = 1; off < 256; off <<= 1) {
        int t = (threadIdx.x >= off) ? sm[threadIdx.x - off] : 0;
        __syncthreads();
        sm[threadIdx.x] += t;
        __syncthreads();
    }
    if (i < n) pre[i] = sm[threadIdx.x] - v;
    if (threadIdx.x == 255) bsum[blockIdx.x] = sm[255];
}
__global__ void k_scan2(int* __restrict__ bsum, int nb) {
    __shared__ int sm[512];
    int v = (threadIdx.x < nb) ? bsum[threadIdx.x] : 0;
    sm[threadIdx.x] = v;
    __syncthreads();
    for (int off = 1; off < 512; off <<= 1) {
        int t = (threadIdx.x >= off) ? sm[threadIdx.x - off] : 0;
        __syncthreads();
        sm[threadIdx.x] += t;
        __syncthreads();
    }
    if (threadIdx.x < nb) bsum[threadIdx.x] = sm[threadIdx.x] - v;
}
__global__ void k_scan3(int* __restrict__ pre, const int* __restrict__ bsum, int n, int E) {
    int i = blockIdx.x * 256 + threadIdx.x;
    if (i < n) pre[i] += bsum[blockIdx.x];
    if (i == 0) pre[n] = E;
}
__global__ void k_dinv2(const int* __restrict__ cnt, float* __restrict__ dinv, int n) {
    int i = blockIdx.x * blockDim.x + threadIdx.x;
    if (i < n) dinv[i] = rsqrtf((float)cnt[i] + 1.0f);
}
__global__ void k_copy(int* __restrict__ dst, const int* __restrict__ src, int n) {
    int i = blockIdx.x * blockDim.x + threadIdx.x;
    if (i < n) dst[i] = src[i];
}
__global__ void k_fill(const void* __restrict__ ei, int* __restrict__ next,
                       int* __restrict__ csr, int E) {
    int e = blockIdx.x * blockDim.x + threadIdx.x;
    if (e >= E) return;
    int s, d; edge_get(ei, E, e, s, d);
    int pos = atomicAdd(&next[d], 1);
    csr[pos] = s;
}

// ---------------------------------------------------------------------------
// split helper + streaming store helpers
// ---------------------------------------------------------------------------
__device__ __forceinline__ void split2(float a, float b,
                                       __nv_bfloat162& hi, __nv_bfloat162& lo) {
    __nv_bfloat16 h0 = __float2bfloat16_rn(a), h1 = __float2bfloat16_rn(b);
    hi = __nv_bfloat162(h0, h1);
    lo = __nv_bfloat162(__float2bfloat16_rn(a - __bfloat162float(h0)),
                        __float2bfloat16_rn(b - __bfloat162float(h1)));
}
__device__ __forceinline__ uint32_t b2u(__nv_bfloat162 v) {
    uint32_t u;
    __builtin_memcpy(&u, &v, 4);
    return u;
}
__device__ __forceinline__ void stwt2(uint32_t* p, uint32_t a, uint32_t b) {
    asm volatile("st.global.wt.v2.b32 [%0], {%1, %2};" :: "l"(p), "r"(a), "r"(b) : "memory");
}
__device__ __forceinline__ void stwt4f(float* p, float4 v) {
    asm volatile("st.global.wt.v4.f32 [%0], {%1, %2, %3, %4};"
                 :: "l"(p), "f"(v.x), "f"(v.y), "f"(v.z), "f"(v.w) : "memory");
}

// ---------------------------------------------------------------------------
// CSR pull aggregation (unchunked, for small tables): L1.
// ---------------------------------------------------------------------------
template<int F4, bool OUT_BF16, bool STREAM>
__global__ __launch_bounds__(256)
void k_csragg(const float* __restrict__ h, float* __restrict__ out,
              __nv_bfloat16* __restrict__ ohi, __nv_bfloat16* __restrict__ olo,
              const int* __restrict__ rowptr, const int* __restrict__ csr,
              const float* __restrict__ dinv, const float* __restrict__ bias, int n) {
    constexpr int NPB = 256 / F4;
    int node = blockIdx.x * NPB + threadIdx.x / F4;
    int lane = threadIdx.x % F4;
    if (node >= n) return;
    int beg = __ldg(&rowptr[node]);
    int end = __ldg(&rowptr[node + 1]);
    const float4* h4 = reinterpret_cast<const float4*>(h);
    float4 acc = make_float4(0.f, 0.f, 0.f, 0.f);
#pragma unroll 4
    for (int j = beg; j < end; j++) {
        int s = __ldg(&csr[j]);
        float w = __ldg(&dinv[s]);
        float4 v = __ldg(&h4[(long long)s * F4 + lane]);
        acc.x += w * v.x; acc.y += w * v.y; acc.z += w * v.z; acc.w += w * v.w;
    }
    float dn = dinv[node];
    float4 hv = __ldg(&h4[(long long)node * F4 + lane]);
    acc.x = (acc.x + dn * hv.x) * dn;
    acc.y = (acc.y + dn * hv.y) * dn;
    acc.z = (acc.z + dn * hv.z) * dn;
    acc.w = (acc.w + dn * hv.w) * dn;
    if (bias) {
        float4 b = reinterpret_cast<const float4*>(bias)[lane];
        acc.x += b.x; acc.y += b.y; acc.z += b.z; acc.w += b.w;
    }
    if (OUT_BF16) {
        __nv_bfloat162 h01, l01, h23, l23;
        split2(acc.x, acc.y, h01, l01);
        split2(acc.z, acc.w, h23, l23);
        long long base = (long long)node * F4 * 2 + lane * 2;   // uint32 units
        if (STREAM) {
            stwt2(reinterpret_cast<uint32_t*>(ohi) + base, b2u(h01), b2u(h23));
            stwt2(reinterpret_cast<uint32_t*>(olo) + base, b2u(l01), b2u(l23));
        } else {
            reinterpret_cast<__nv_bfloat162*>(ohi)[base]     = h01;
            reinterpret_cast<__nv_bfloat162*>(ohi)[base + 1] = h23;
            reinterpret_cast<__nv_bfloat162*>(olo)[base]     = l01;
            reinterpret_cast<__nv_bfloat162*>(olo)[base + 1] = l23;
        }
    } else {
        if (STREAM)
            stwt4f(out + ((long long)node * F4 + lane) * 4, acc);
        else
            reinterpret_cast<float4*>(out)[(long long)node * F4 + lane] = acc;
    }
}

// ---------------------------------------------------------------------------
// Feature-chunked CSR pull aggregation (L2/L3/L4). blockIdx.y = chunk (slow
// axis -> all concurrent CTAs gather from the same L2-resident sub-table).
// 256-thread blocks, streaming (wt) outputs. Arithmetic identical to the
// unchunked version per output element.
// ---------------------------------------------------------------------------
template<int F4TOT, int F4CHUNK, bool OUT_BF16>
__global__ __launch_bounds__(256)
void k_csragg_chunk(const float* __restrict__ h, float* __restrict__ out,
                    __nv_bfloat16* __restrict__ ohi, __nv_bfloat16* __restrict__ olo,
                    const int* __restrict__ rowptr, const int* __restrict__ csr,
                    const float* __restrict__ dinv, const float* __restrict__ bias, int n) {
    constexpr int NPB = 256 / F4CHUNK;
    int node = blockIdx.x * NPB + threadIdx.x / F4CHUNK;
    int lane = threadIdx.x % F4CHUNK;
    if (node >= n) return;
    int coff = blockIdx.y * F4CHUNK + lane;        // float4 index within row
    int beg = __ldg(&rowptr[node]);
    int end = __ldg(&rowptr[node + 1]);
    const float4* h4 = reinterpret_cast<const float4*>(h);
    float4 acc = make_float4(0.f, 0.f, 0.f, 0.f);
#pragma unroll 4
    for (int j = beg; j < end; j++) {
        int s = __ldg(&csr[j]);
        float w = __ldg(&dinv[s]);
        float4 v = __ldg(&h4[(long long)s * F4TOT + coff]);
        acc.x += w * v.x; acc.y += w * v.y; acc.z += w * v.z; acc.w += w * v.w;
    }
    float dn = dinv[node];
    float4 hv = __ldg(&h4[(long long)node * F4TOT + coff]);
    acc.x = (acc.x + dn * hv.x) * dn;
    acc.y = (acc.y + dn * hv.y) * dn;
    acc.z = (acc.z + dn * hv.z) * dn;
    acc.w = (acc.w + dn * hv.w) * dn;
    if (bias) {
        float4 b = reinterpret_cast<const float4*>(bias)[coff];
        acc.x += b.x; acc.y += b.y; acc.z += b.z; acc.w += b.w;
    }
    if (OUT_BF16) {
        __nv_bfloat162 h01, l01, h23, l23;
        split2(acc.x, acc.y, h01, l01);
        split2(acc.z, acc.w, h23, l23);
        long long base = (long long)node * F4TOT * 2 + coff * 2;   // uint32 units
        stwt2(reinterpret_cast<uint32_t*>(ohi) + base, b2u(h01), b2u(h23));
        stwt2(reinterpret_cast<uint32_t*>(olo) + base, b2u(l01), b2u(l23));
    } else {
        stwt4f(out + ((long long)node * F4TOT + coff) * 4, acc);
    }
}

// F=6 variant (8 threads per node)
__global__ __launch_bounds__(256)
void k_csragg6(const float* __restrict__ z, float* __restrict__ out,
               const int* __restrict__ rowptr, const int* __restrict__ csr,
               const float* __restrict__ dinv, const float* __restrict__ bias, int n) {
    int node = blockIdx.x * 32 + threadIdx.x / 8;
    int lane = threadIdx.x % 8;
    if (node >= n) return;
    int beg = __ldg(&rowptr[node]);
    int end = __ldg(&rowptr[node + 1]);
    float acc = 0.f;
    for (int j = beg; j < end; j++) {
        int s = __ldg(&csr[j]);
        if (lane < 6) acc += __ldg(&dinv[s]) * __ldg(&z[(long long)s * 6 + lane]);
    }
    float dn = dinv[node];
    if (lane < 6)
        out[(long long)node * 6 + lane] =
            (acc + dn * __ldg(&z[(long long)node * 6 + lane])) * dn + bias[lane];
}

// W[K,N] -> Wt_hi/lo[N,K]
__global__ void k_wsplit(const float* __restrict__ W, __nv_bfloat16* __restrict__ th,
                         __nv_bfloat16* __restrict__ tl, int K, int N) {
    int i = blockIdx.x * blockDim.x + threadIdx.x;
    if (i >= K * N) return;
    int k = i / N, n = i - k * N;
    float w = W[i];
    __nv_bfloat16 h = __float2bfloat16_rn(w);
    __nv_bfloat16 l = __float2bfloat16_rn(w - __bfloat162float(h));
    th[(long long)n * K + k] = h;
    tl[(long long)n * K + k] = l;
}

// ---------------------------------------------------------------------------
// mma.sync bf16 GEMM (3-term fp32 split), 128x128x32 tile, cp.async 2-stage.
// ---------------------------------------------------------------------------
__device__ __forceinline__ uint32_t smem_u32(const void* p) {
    uint32_t a;
    asm("{ .reg .u64 t; cvta.to.shared.u64 t, %1; cvt.u32.u64 %0, t; }" : "=r"(a) : "l"(p));
    return a;
}
__device__ __forceinline__ void cp16(uint32_t dst, const void* src, bool v) {
    asm volatile("cp.async.cg.shared.global [%0], [%1], 16, %2;"
                 :: "r"(dst), "l"(src), "r"(v ? 16 : 0) : "memory");
}
__device__ __forceinline__ uint32_t lds32(const __nv_bfloat16* p) {
    return *reinterpret_cast<const uint32_t*>(p);
}
__device__ __forceinline__ void mma16816(float* c, const uint32_t* a, const uint32_t* b) {
    asm volatile("mma.sync.aligned.m16n8k16.row.col.f32.bf16.bf16.f32 "
                 "{%0,%1,%2,%3}, {%4,%5,%6,%7}, {%8,%9}, {%0,%1,%2,%3};"
                 : "+f"(c[0]), "+f"(c[1]), "+f"(c[2]), "+f"(c[3])
                 : "r"(a[0]), "r"(a[1]), "r"(a[2]), "r"(a[3]), "r"(b[0]), "r"(b[1]));
}

#define STG_STRIDE 20480
#define ROW_ST 40

template<bool RELU, bool HAS_BIAS, bool OUT_BF16>
__global__ __launch_bounds__(256)
void k_mma(const __nv_bfloat16* __restrict__ Ah, const __nv_bfloat16* __restrict__ Al,
           const __nv_bfloat16* __restrict__ Bh, const __nv_bfloat16* __restrict__ Bl,
           const float* __restrict__ bias, float* __restrict__ C,
           __nv_bfloat16* __restrict__ Chi, __nv_bfloat16* __restrict__ Clo,
           int M, int K, int N) {
    extern __shared__ __align__(16) __nv_bfloat16 sm[];
    const int tid = threadIdx.x;
    const int wid = tid >> 5, lane = tid & 31;
    const int wm = wid & 3, wn = wid >> 2;
    const int gid = lane >> 2, tq = lane & 3;
    const int m0 = blockIdx.y * 128, n0 = blockIdx.x * 128;

    float acc[2][8][4];
#pragma unroll
    for (int a = 0; a < 2; a++)
#pragma unroll
        for (int b = 0; b < 8; b++)
#pragma unroll
            for (int c = 0; c < 4; c++) acc[a][b][c] = 0.f;

    const int nK = K >> 5;

    auto issue = [&](int it, int s) {
        int k0 = it << 5;
#pragma unroll
        for (int i = 0; i < 2; i++) {
            int idx = tid + i * 256;
            int row = idx >> 2, g = idx & 3;
            uint32_t so = (uint32_t)s * STG_STRIDE + row * ROW_ST + g * 8;
            bool av = (m0 + row) < M;
            size_t gA = (size_t)(m0 + row) * K + k0 + g * 8;
            cp16(smem_u32(sm + so),          Ah + (av ? gA : 0), av);
            cp16(smem_u32(sm + so + 5120),   Al + (av ? gA : 0), av);
            size_t gB = (size_t)(n0 + row) * K + k0 + g * 8;
            cp16(smem_u32(sm + so + 10240),  Bh + gB, true);
            cp16(smem_u32(sm + so + 15360),  Bl + gB, true);
        }
        asm volatile("cp.async.commit_group;" ::: "memory");
    };

    issue(0, 0);
    for (int it = 0; it < nK; ++it) {
        if (it + 1 < nK) {
            issue(it + 1, (it + 1) & 1);
            asm volatile("cp.async.wait_group 1;" ::: "memory");
        } else {
            asm volatile("cp.async.wait_group 0;" ::: "memory");
        }
        __syncthreads();

        const __nv_bfloat16* sbase = sm + (uint32_t)(it & 1) * STG_STRIDE;
#pragma unroll
        for (int kk = 0; kk < 32; kk += 16) {
            uint32_t ah[2][4], al[2][4];
#pragma unroll
            for (int mt = 0; mt < 2; mt++) {
                const __nv_bfloat16* p = sbase + (wm * 32 + mt * 16 + gid) * ROW_ST + kk + tq * 2;
                ah[mt][0] = lds32(p);
                ah[mt][1] = lds32(p + 8 * ROW_ST);
                ah[mt][2] = lds32(p + 8);
                ah[mt][3] = lds32(p + 8 * ROW_ST + 8);
                al[mt][0] = lds32(p + 5120);
                al[mt][1] = lds32(p + 5120 + 8 * ROW_ST);
                al[mt][2] = lds32(p + 5120 + 8);
                al[mt][3] = lds32(p + 5120 + 8 * ROW_ST + 8);
            }
#pragma unroll
            for (int nt = 0; nt < 8; nt++) {
                const __nv_bfloat16* q = sbase + 10240 + (wn * 64 + nt * 8 + gid) * ROW_ST + kk + tq * 2;
                uint32_t bh[2] = { lds32(q), lds32(q + 8) };
                uint32_t bl[2] = { lds32(q + 5120), lds32(q + 5120 + 8) };
#pragma unroll
                for (int mt = 0; mt < 2; mt++) {
                    mma16816(acc[mt][nt], ah[mt], bh);
                    mma16816(acc[mt][nt], ah[mt], bl);
                    mma16816(acc[mt][nt], al[mt], bh);
                }
            }
        }
        __syncthreads();
    }

#pragma unroll
    for (int mt = 0; mt < 2; mt++) {
#pragma unroll
        for (int half = 0; half < 2; half++) {
            int row = m0 + wm * 32 + mt * 16 + gid + half * 8;
            if (row >= M) continue;
#pragma unroll
            for (int nt = 0; nt < 8; nt++) {
                int col = nt * 8 + tq * 2;
                float v0 = acc[mt][nt][half * 2 + 0];
                float v1 = acc[mt][nt][half * 2 + 1];
                if (HAS_BIAS) {
                    const float* bp = bias + n0 + wn * 64 + col;
                    v0 += bp[0]; v1 += bp[1];
                }
                if (RELU) { v0 = fmaxf(v0, 0.f); v1 = fmaxf(v1, 0.f); }
                if (OUT_BF16) {
                    __nv_bfloat162 h, l;
                    split2(v0, v1, h, l);
                    size_t o = ((size_t)row * N + n0 + wn * 64 + col) >> 1;
                    reinterpret_cast<__nv_bfloat162*>(Chi)[o] = h;
                    reinterpret_cast<__nv_bfloat162*>(Clo)[o] = l;
                } else {
                    float* cp = C + (size_t)row * N + n0 + wn * 64;
                    *reinterpret_cast<float2*>(cp + col) = make_float2(v0, v1);
                }
            }
        }
    }
}

// ---------------------------------------------------------------------------
// FFMA SGEMM (L1, K=32)
// ---------------------------------------------------------------------------
template<bool RELU_OUT, bool HAS_BIAS>
__global__ __launch_bounds__(256)
void k_sgemm(const float* __restrict__ A, const float* __restrict__ B,
             const float* __restrict__ bias, float* __restrict__ C,
             int M, int K, int N) {
    constexpr int BM = 128, BN = 128, BK = 8, TM = 8, TN = 8;
    __shared__ float As[BK][BM];
    __shared__ float Bs[BK][BN];
    int tid = threadIdx.x;
    int tr = tid / 16, tc = tid % 16;
    float acc[TM][TN];
#pragma unroll
    for (int i = 0; i < TM; i++)
#pragma unroll
        for (int j = 0; j < TN; j++) acc[i][j] = 0.f;
    int aRow = tid >> 1, aCol = (tid & 1) << 2;
    int bRow = tid >> 5, bCol = (tid & 31) << 2;
    long long aGRow = (long long)blockIdx.y * BM + aRow;
    const bool aValid = aGRow < M;
    const float* Aptr = A + aGRow * (long long)K + aCol;
    const float* Bptr = B + (long long)bRow * N + (long long)blockIdx.x * BN + bCol;
    for (int k0 = 0; k0 < K; k0 += BK) {
        float4 av = make_float4(0.f, 0.f, 0.f, 0.f);
        if (aValid) av = *reinterpret_cast<const float4*>(Aptr + k0);
        As[aCol + 0][aRow] = av.x; As[aCol + 1][aRow] = av.y;
        As[aCol + 2][aRow] = av.z; As[aCol + 3][aRow] = av.w;
        float4 bv = *reinterpret_cast<const float4*>(Bptr + (long long)k0 * N);
        *reinterpret_cast<float4*>(&Bs[bRow][bCol]) = bv;
        __syncthreads();
#pragma unroll
        for (int k = 0; k < BK; k++) {
            float rm[TM], rn[TN];
#pragma unroll
            for (int i = 0; i < TM; i++) rm[i] = As[k][tr * TM + i];
#pragma unroll
            for (int j = 0; j < TN; j++) rn[j] = Bs[k][tc * TN + j];
#pragma unroll
            for (int i = 0; i < TM; i++)
#pragma unroll
                for (int j = 0; j < TN; j++) acc[i][j] += rm[i] * rn[j];
        }
        __syncthreads();
    }
#pragma unroll
    for (int i = 0; i < TM; i++) {
        long long row = (long long)blockIdx.y * BM + tr * TM + i;
        if (row >= M) continue;
#pragma unroll
        for (int j = 0; j < TN; j += 4) {
            int col = blockIdx.x * BN + tc * TN + j;
            float4 v = make_float4(acc[i][j], acc[i][j + 1], acc[i][j + 2], acc[i][j + 3]);
            if (HAS_BIAS) {
                float4 bb = *reinterpret_cast<const float4*>(bias + col);
                v.x += bb.x; v.y += bb.y; v.z += bb.z; v.w += bb.w;
            }
            if (RELU_OUT) {
                v.x = fmaxf(v.x, 0.f); v.y = fmaxf(v.y, 0.f);
                v.z = fmaxf(v.z, 0.f); v.w = fmaxf(v.w, 0.f);
            }
            *reinterpret_cast<float4*>(C + row * (long long)N + col) = v;
        }
    }
}

// ---------------------------------------------------------------------------
// L5: z = relu(A[M,256]) @ W[256,6]
// ---------------------------------------------------------------------------
__global__ void k_gemm_relu_256x6(const float* __restrict__ A, const float* __restrict__ W,
                                  float* __restrict__ C, int M) {
    __shared__ float Ws[256 * 6];
    for (int i = threadIdx.x; i < 256 * 6; i += blockDim.x) Ws[i] = W[i];
    __syncthreads();
    int warp = threadIdx.x >> 5, lane = threadIdx.x & 31;
    long long row = (long long)blockIdx.x * 8 + warp;
    if (row >= M) return;
    float a0 = 0.f, a1 = 0.f, a2 = 0.f, a3 = 0.f, a4 = 0.f, a5 = 0.f;
    const float* a = A + row * 256;
#pragma unroll
    for (int k0 = 0; k0 < 256; k0 += 32) {
        float av = fmaxf(a[k0 + lane], 0.f);
        const float* w = &Ws[(k0 + lane) * 6];
        a0 += av * w[0]; a1 += av * w[1]; a2 += av * w[2];
        a3 += av * w[3]; a4 += av * w[4]; a5 += av * w[5];
    }
#pragma unroll
    for (int off = 16; off > 0; off >>= 1) {
        a0 += __shfl_down_sync(0xffffffffu, a0, off);
        a1 += __shfl_down_sync(0xffffffffu, a1, off);
        a2 += __shfl_down_sync(0xffffffffu, a2, off);
        a3 += __shfl_down_sync(0xffffffffu, a3, off);
        a4 += __shfl_down_sync(0xffffffffu, a4, off);
        a5 += __shfl_down_sync(0xffffffffu, a5, off);
    }
    if (lane == 0) {
        float* c = C + row * 6;
        c[0] = a0; c[1] = a1; c[2] = a2; c[3] = a3; c[4] = a4; c[5] = a5;
    }
}

// ---------------------------------------------------------------------------

static inline unsigned cdiv(long long a, long long b) { return (unsigned)((a + b - 1) / b); }

extern "C" void kernel_launch(void* const* d_in, const int* in_sizes, int n_in,
                              void* d_out, int out_size) {
    const float* x  = (const float*)d_in[0];
    const void*  ei = d_in[1];
    const float* W1 = (const float*)d_in[2];  const float* b1 = (const float*)d_in[3];
    const float* W2 = (const float*)d_in[4];  const float* b2 = (const float*)d_in[5];
    const float* W3 = (const float*)d_in[6];  const float* b3 = (const float*)d_in[7];
    const float* W4 = (const float*)d_in[8];  const float* b4 = (const float*)d_in[9];
    const float* W5 = (const float*)d_in[10]; const float* b5 = (const float*)d_in[11];

    int N = in_sizes[0] / 32;
    int E = in_sizes[1] / 2;
    float* out = (float*)d_out;

    float *bufA, *bufB, *z6, *dinv;
    int *cnt, *rowptr, *nxt, *csr, *bsum;
    __nv_bfloat16 *Ahi, *Alo, *Chi, *Clo, *W2h, *W2l, *W3h, *W3l, *W4h, *W4l;
    cudaGetSymbolAddress((void**)&bufA, g_bufA);
    cudaGetSymbolAddress((void**)&bufB, g_bufB);
    cudaGetSymbolAddress((void**)&z6,   g_z6);
    cudaGetSymbolAddress((void**)&dinv, g_dinv);
    cudaGetSymbolAddress((void**)&cnt,    g_cnt);
    cudaGetSymbolAddress((void**)&rowptr, g_rowptr);
    cudaGetSymbolAddress((void**)&nxt,    g_next);
    cudaGetSymbolAddress((void**)&csr,    g_csr);
    cudaGetSymbolAddress((void**)&bsum,   g_bsum);
    cudaGetSymbolAddress((void**)&Ahi,  g_Ahi);
    cudaGetSymbolAddress((void**)&Alo,  g_Alo);
    cudaGetSymbolAddress((void**)&Chi,  g_Chi);
    cudaGetSymbolAddress((void**)&Clo,  g_Clo);
    cudaGetSymbolAddress((void**)&W2h,  g_W2h); cudaGetSymbolAddress((void**)&W2l, g_W2l);
    cudaGetSymbolAddress((void**)&W3h,  g_W3h); cudaGetSymbolAddress((void**)&W3l, g_W3l);
    cudaGetSymbolAddress((void**)&W4h,  g_W4h); cudaGetSymbolAddress((void**)&W4l, g_W4l);

    const int SMEM_DYN = 2 * STG_STRIDE * 2;   // 81920 B
    cudaFuncSetAttribute((const void*)k_mma<true, true, false>,  cudaFuncAttributeMaxDynamicSharedMemorySize, SMEM_DYN);
    cudaFuncSetAttribute((const void*)k_mma<true, true, true>,   cudaFuncAttributeMaxDynamicSharedMemorySize, SMEM_DYN);
    cudaFuncSetAttribute((const void*)k_mma<false, false, false>, cudaFuncAttributeMaxDynamicSharedMemorySize, SMEM_DYN);

    // --- edge dtype + CSR build ---
    int npairs = (2 * E < 8192) ? E : 4096;
    k_detect<<<1, 256>>>((const unsigned*)ei, npairs);
    k_zeroi<<<cdiv(N, 256), 256>>>(cnt, N);
    k_count<<<cdiv(E, 256), 256>>>(ei, cnt, E);
    int nb = cdiv(N, 256);
    k_scan1<<<nb, 256>>>(cnt, rowptr, bsum, N);
    k_scan2<<<1, 512>>>(bsum, nb);
    k_scan3<<<nb, 256>>>(rowptr, bsum, N, E);
    k_dinv2<<<cdiv(N, 256), 256>>>(cnt, dinv, N);
    k_copy<<<cdiv(N, 256), 256>>>(nxt, rowptr, N);
    k_fill<<<cdiv(E, 256), 256>>>(ei, nxt, csr, E);

    // --- weight transposes + splits ---
    k_wsplit<<<cdiv(256 * 1024, 256), 256>>>(W2, W2h, W2l, 256, 1024);
    k_wsplit<<<cdiv(1024 * 1024, 256), 256>>>(W3, W3h, W3l, 1024, 1024);
    k_wsplit<<<cdiv(1024 * 256, 256), 256>>>(W4, W4h, W4l, 1024, 256);

    // --- L1: t = A*x (F=32) -> bufA ; h1 = relu(t@W1+b1) -> bufB [N,256] ---
    k_csragg<8, false, false><<<cdiv(N, 32), 256>>>(x, bufA, nullptr, nullptr, rowptr, csr, dinv, nullptr, N);
    k_sgemm<true, true><<<dim3(2, cdiv(N, 128)), 256>>>(bufA, W1, b1, bufB, N, 32, 256);

    // --- L2: t = A*h1 (F=256, 2-chunk, split-fused) -> Ahi/Alo ;
    //     h2 = relu(t@W2+b2) -> bufB [N,1024] ---
    k_csragg_chunk<64, 32, true><<<dim3(cdiv(N, 8), 2), 256>>>(bufB, nullptr, Ahi, Alo, rowptr, csr, dinv, nullptr, N);
    k_mma<true, true, false><<<dim3(8, cdiv(N, 128)), 256, SMEM_DYN>>>(Ahi, Alo, W2h, W2l, b2, bufB, nullptr, nullptr, N, 256, 1024);

    // --- L3: t = A*h2 (F=1024, 4-chunk) -> Ahi/Alo ; h3 = relu(t@W3+b3) -> Chi/Clo ---
    k_csragg_chunk<256, 64, true><<<dim3(cdiv(N, 4), 4), 256>>>(bufB, nullptr, Ahi, Alo, rowptr, csr, dinv, nullptr, N);
    k_mma<true, true, true><<<dim3(8, cdiv(N, 128)), 256, SMEM_DYN>>>(Ahi, Alo, W3h, W3l, b3, nullptr, Chi, Clo, N, 1024, 1024);

    // --- L4 (transform-first): z = h3@W4 -> bufA [N,256];
    //     t = A*z + b4 -> bufB (2-chunk, fp32 out) ---
    k_mma<false, false, false><<<dim3(2, cdiv(N, 128)), 256, SMEM_DYN>>>(Chi, Clo, W4h, W4l, nullptr, bufA, nullptr, nullptr, N, 1024, 256);
    k_csragg_chunk<64, 32, false><<<dim3(cdiv(N, 8), 2), 256>>>(bufA, bufB, nullptr, nullptr, rowptr, csr, dinv, b4, N);

    // --- L5: z6 = relu(bufB)@W5 ; out = A*z6 + b5 ---
    k_gemm_relu_256x6<<<cdiv(N, 8), 256>>>(bufB, W5, z6, N);
    k_csragg6<<<cdiv(N, 32), 256>>>(z6, out, rowptr, csr, dinv, b5, N);
}